// round 3
// baseline (speedup 1.0000x reference)
#include <cuda_runtime.h>
#include <math.h>

#define CDIM 128
#define BT 64
#define NTHREADS 256
#define EPSF 1e-8f

// Device scratch (allocation-free rule): M = Wq @ Wk^T for both branches.
__device__ float g_M[2][CDIM * CDIM];

__device__ __forceinline__ float4 lds4(const float* p) {
    return *reinterpret_cast<const float4*>(p);
}

// ---------------------------------------------------------------------------
// Prep kernel: g_M[0] = Wq_m @ Wk_m^T, g_M[1] = Wq_d @ Wk_d^T
// grid: 256 blocks (which = bid>>7, row i = bid&127), 128 threads (p = tid)
// ---------------------------------------------------------------------------
__global__ void prep_kernel(const float* __restrict__ Wq_m, const float* __restrict__ Wk_m,
                            const float* __restrict__ Wq_d, const float* __restrict__ Wk_d) {
    __shared__ float qrow[CDIM];
    int which = blockIdx.x >> 7;
    int i = blockIdx.x & 127;
    const float* Wq = which ? Wq_d : Wq_m;
    const float* Wk = which ? Wk_d : Wk_m;
    if (threadIdx.x < CDIM) qrow[threadIdx.x] = Wq[i * CDIM + threadIdx.x];
    __syncthreads();
    int p = threadIdx.x;
    const float4* krow = reinterpret_cast<const float4*>(Wk + p * CDIM);
    float s = 0.f;
#pragma unroll
    for (int c4 = 0; c4 < CDIM / 4; ++c4) {
        float4 kv = krow[c4];
        s = fmaf(qrow[c4 * 4 + 0], kv.x, s);
        s = fmaf(qrow[c4 * 4 + 1], kv.y, s);
        s = fmaf(qrow[c4 * 4 + 2], kv.z, s);
        s = fmaf(qrow[c4 * 4 + 3], kv.w, s);
    }
    g_M[which][i * CDIM + p] = s;
}

// ---------------------------------------------------------------------------
// GEMM microkernel: acc[4][8] += A[64x128] @ W[128x128] tile.
// Thread (rg,cg): rows rbase..rbase+3, cols cbase..cbase+7.
// ---------------------------------------------------------------------------
__device__ __forceinline__ void gemm64(const float* __restrict__ As,
                                       const float* __restrict__ Ws,
                                       int rbase, int cbase, float acc[4][8]) {
#pragma unroll 1
    for (int k4 = 0; k4 < CDIM / 4; ++k4) {
        int k = k4 * 4;
        float a[4][4];
#pragma unroll
        for (int i = 0; i < 4; ++i) {
            float4 v = lds4(As + (rbase + i) * CDIM + k);
            a[i][0] = v.x; a[i][1] = v.y; a[i][2] = v.z; a[i][3] = v.w;
        }
#pragma unroll
        for (int kk = 0; kk < 4; ++kk) {
            float4 w0 = lds4(Ws + (k + kk) * CDIM + cbase);
            float4 w1 = lds4(Ws + (k + kk) * CDIM + cbase + 4);
            float wv[8] = {w0.x, w0.y, w0.z, w0.w, w1.x, w1.y, w1.z, w1.w};
#pragma unroll
            for (int i = 0; i < 4; ++i)
#pragma unroll
                for (int j = 0; j < 8; ++j)
                    acc[i][j] = fmaf(a[i][kk], wv[j], acc[i][j]);
        }
    }
}

// A is a per-row linear combination (ca[i]*M + cb[i]*D) built on the fly.
__device__ __forceinline__ void gemm64_comb(const float* __restrict__ Ma,
                                            const float* __restrict__ Db,
                                            const float* __restrict__ Ws,
                                            int rbase, int cbase,
                                            const float ca[4], const float cb[4],
                                            float acc[4][8]) {
#pragma unroll 1
    for (int k4 = 0; k4 < CDIM / 4; ++k4) {
        int k = k4 * 4;
        float a[4][4];
#pragma unroll
        for (int i = 0; i < 4; ++i) {
            float4 mv = lds4(Ma + (rbase + i) * CDIM + k);
            float4 dv = lds4(Db + (rbase + i) * CDIM + k);
            a[i][0] = ca[i] * mv.x + cb[i] * dv.x;
            a[i][1] = ca[i] * mv.y + cb[i] * dv.y;
            a[i][2] = ca[i] * mv.z + cb[i] * dv.z;
            a[i][3] = ca[i] * mv.w + cb[i] * dv.w;
        }
#pragma unroll
        for (int kk = 0; kk < 4; ++kk) {
            float4 w0 = lds4(Ws + (k + kk) * CDIM + cbase);
            float4 w1 = lds4(Ws + (k + kk) * CDIM + cbase + 4);
            float wv[8] = {w0.x, w0.y, w0.z, w0.w, w1.x, w1.y, w1.z, w1.w};
#pragma unroll
            for (int i = 0; i < 4; ++i)
#pragma unroll
                for (int j = 0; j < 8; ++j)
                    acc[i][j] = fmaf(a[i][kk], wv[j], acc[i][j]);
        }
    }
}

__device__ __forceinline__ void load_w(const float* __restrict__ g, float* s) {
    const float4* gs = reinterpret_cast<const float4*>(g);
    float4* ss = reinterpret_cast<float4*>(s);
    for (int i = threadIdx.x; i < CDIM * CDIM / 4; i += NTHREADS) ss[i] = gs[i];
}

// SMEM float offsets
#define OFF_M    0
#define OFF_D    8192
#define OFF_X1M  16384
#define OFF_X1D  24576
#define OFF_W    32768
#define OFF_R0   49152
#define OFF_R1   50176
#define OFF_SA   51200
#define OFF_SB   51264
#define OFF_W2   51328
#define SMEM_FLOATS 51456
#define SMEM_BYTES (SMEM_FLOATS * 4)

__global__ __launch_bounds__(NTHREADS, 1)
void mdi_kernel(const float* __restrict__ em, const float* __restrict__ ed,
                const float* __restrict__ Wgcn,
                const float* __restrict__ Wv_m, const float* __restrict__ Wv_d,
                const float* __restrict__ W1, const float* __restrict__ W2,
                float* __restrict__ out) {
    extern __shared__ float sh[];
    float* Ms  = sh + OFF_M;
    float* Ds  = sh + OFF_D;
    float* X1m = sh + OFF_X1M;
    float* X1d = sh + OFF_X1D;
    float* Ws  = sh + OFF_W;
    float* R0  = sh + OFF_R0;
    float* R1  = sh + OFF_R1;
    float* SA  = sh + OFF_SA;
    float* SB  = sh + OFF_SB;
    float* SW2 = sh + OFF_W2;

    const int tid = threadIdx.x;
    const int cg = tid & 15;
    const int rg = tid >> 4;
    const int rbase = rg * 4;
    const int cbase = cg * 8;
    const int b0 = blockIdx.x * BT;

    // ---- Load em/ed tiles + W2 ----
    {
        const float4* gm = reinterpret_cast<const float4*>(em + (size_t)b0 * CDIM);
        const float4* gd = reinterpret_cast<const float4*>(ed + (size_t)b0 * CDIM);
        float4* sm = reinterpret_cast<float4*>(Ms);
        float4* sd = reinterpret_cast<float4*>(Ds);
        for (int i = tid; i < BT * CDIM / 4; i += NTHREADS) { sm[i] = gm[i]; sd[i] = gd[i]; }
        if (tid < CDIM) SW2[tid] = W2[tid];
    }
    __syncthreads();

    // ---- E1: per-batch scalars (manhattan + cosine -> pL entries a, b) ----
    {
        int r = tid >> 2, part = tid & 3;
        const float* mrow = Ms + r * CDIM;
        const float* drow = Ds + r * CDIM;
        float dman = 0.f, sm2 = 0.f, sd2 = 0.f, md = 0.f;
        int k0 = part * 32;
#pragma unroll
        for (int k = 0; k < 32; k += 4) {
            float4 mv = lds4(mrow + k0 + k);
            float4 dv = lds4(drow + k0 + k);
            dman += fabsf(mv.x - dv.x) + fabsf(mv.y - dv.y) + fabsf(mv.z - dv.z) + fabsf(mv.w - dv.w);
            sm2 += mv.x * mv.x + mv.y * mv.y + mv.z * mv.z + mv.w * mv.w;
            sd2 += dv.x * dv.x + dv.y * dv.y + dv.z * dv.z + dv.w * dv.w;
            md  += mv.x * dv.x + mv.y * dv.y + mv.z * dv.z + mv.w * dv.w;
        }
        R0[0   + r * 4 + part] = dman;
        R0[256 + r * 4 + part] = sm2;
        R0[512 + r * 4 + part] = sd2;
        R0[768 + r * 4 + part] = md;
    }
    __syncthreads();
    if (tid < BT) {
        int b4 = tid * 4;
        float dman = R0[b4] + R0[b4 + 1] + R0[b4 + 2] + R0[b4 + 3];
        float sm2  = R0[256 + b4] + R0[257 + b4] + R0[258 + b4] + R0[259 + b4];
        float sd2  = R0[512 + b4] + R0[513 + b4] + R0[514 + b4] + R0[515 + b4];
        float md   = R0[768 + b4] + R0[769 + b4] + R0[770 + b4] + R0[771 + b4];
        // manhattan branch: dman >= 0 so lrelu is identity
        float s3 = 1.f / (1.f + dman);
        // cosine branch
        float c = md / (sqrtf(sm2 + EPSF) * sqrtf(sd2 + EPSF));
        if (c < 0.f) c *= 0.01f;            // leaky relu
        float s1 = 1.f / (1.f + c);          // deg = 1 + c >= 0.99 > EPS
        SA[tid] = fminf(s3, s1);             // diagonal of pL
        SB[tid] = fminf(dman * s3, c * s1);  // off-diagonal of pL
    }
    __syncthreads();

    // ---- S2: GCN. u0 = a*m + b*d ; u1 = b*m + a*d ; x1 = relu(u@Wgcn) + x0 ----
    load_w(Wgcn, Ws);
    __syncthreads();
    {
        float ca[4], cb[4];
#pragma unroll
        for (int i = 0; i < 4; ++i) { ca[i] = SA[rbase + i]; cb[i] = SB[rbase + i]; }

        float acc[4][8] = {{0.f}};
        gemm64_comb(Ms, Ds, Ws, rbase, cbase, ca, cb, acc);   // u0 @ Wgcn
#pragma unroll
        for (int i = 0; i < 4; ++i)
#pragma unroll
            for (int j = 0; j < 8; ++j) {
                int idx = (rbase + i) * CDIM + cbase + j;
                X1m[idx] = fmaxf(acc[i][j], 0.f) + Ms[idx];
            }

        float acc2[4][8] = {{0.f}};
        gemm64_comb(Ms, Ds, Ws, rbase, cbase, cb, ca, acc2);  // u1 @ Wgcn
#pragma unroll
        for (int i = 0; i < 4; ++i)
#pragma unroll
            for (int j = 0; j < 8; ++j) {
                int idx = (rbase + i) * CDIM + cbase + j;
                X1d[idx] = fmaxf(acc2[i][j], 0.f) + Ds[idx];
            }
    }
    __syncthreads();

    const float ISQRTC = 0.0883883476483184f;  // 1/sqrt(128)

    // ---- S4/S5 branch m: t = x1m@Mm; scores; softmax; z_m -> X1m ----
    load_w(g_M[0], Ws);
    __syncthreads();
    {
        float acc[4][8] = {{0.f}};
        gemm64(X1m, Ws, rbase, cbase, acc);
#pragma unroll
        for (int i = 0; i < 4; ++i) {
            float q0 = 0.f, q1 = 0.f;
#pragma unroll
            for (int j = 0; j < 8; ++j) {
                int idx = (rbase + i) * CDIM + cbase + j;
                q0 = fmaf(acc[i][j], Ms[idx], q0);
                q1 = fmaf(acc[i][j], X1m[idx], q1);
            }
            R0[(rbase + i) * 16 + cg] = q0;
            R1[(rbase + i) * 16 + cg] = q1;
        }
    }
    __syncthreads();
    if (tid < BT) {
        float s0 = 0.f, s1v = 0.f;
#pragma unroll
        for (int g = 0; g < 16; ++g) { s0 += R0[tid * 16 + g]; s1v += R1[tid * 16 + g]; }
        s0 *= ISQRTC; s1v *= ISQRTC;
        float mx = fmaxf(s0, s1v);
        float e0 = expf(s0 - mx), e1 = expf(s1v - mx);
        float inv = 1.f / (e0 + e1);
        SA[tid] = e0 * inv;
        SB[tid] = e1 * inv;
    }
    __syncthreads();
    {
        float4* xm = reinterpret_cast<float4*>(X1m);
        const float4* mm = reinterpret_cast<const float4*>(Ms);
        for (int i4 = tid; i4 < BT * CDIM / 4; i4 += NTHREADS) {
            int r = i4 >> 5;
            float a0 = SA[r], a1 = SB[r];
            float4 mv = mm[i4], xv = xm[i4];
            xv.x = a0 * mv.x + a1 * xv.x;
            xv.y = a0 * mv.y + a1 * xv.y;
            xv.z = a0 * mv.z + a1 * xv.z;
            xv.w = a0 * mv.w + a1 * xv.w;
            xm[i4] = xv;
        }
    }
    __syncthreads();

    // ---- S4/S5 branch d ----
    load_w(g_M[1], Ws);
    __syncthreads();
    {
        float acc[4][8] = {{0.f}};
        gemm64(X1d, Ws, rbase, cbase, acc);
#pragma unroll
        for (int i = 0; i < 4; ++i) {
            float q0 = 0.f, q1 = 0.f;
#pragma unroll
            for (int j = 0; j < 8; ++j) {
                int idx = (rbase + i) * CDIM + cbase + j;
                q0 = fmaf(acc[i][j], Ds[idx], q0);
                q1 = fmaf(acc[i][j], X1d[idx], q1);
            }
            R0[(rbase + i) * 16 + cg] = q0;
            R1[(rbase + i) * 16 + cg] = q1;
        }
    }
    __syncthreads();
    if (tid < BT) {
        float s0 = 0.f, s1v = 0.f;
#pragma unroll
        for (int g = 0; g < 16; ++g) { s0 += R0[tid * 16 + g]; s1v += R1[tid * 16 + g]; }
        s0 *= ISQRTC; s1v *= ISQRTC;
        float mx = fmaxf(s0, s1v);
        float e0 = expf(s0 - mx), e1 = expf(s1v - mx);
        float inv = 1.f / (e0 + e1);
        SA[tid] = e0 * inv;
        SB[tid] = e1 * inv;
    }
    __syncthreads();
    {
        float4* xd = reinterpret_cast<float4*>(X1d);
        const float4* dd = reinterpret_cast<const float4*>(Ds);
        for (int i4 = tid; i4 < BT * CDIM / 4; i4 += NTHREADS) {
            int r = i4 >> 5;
            float a0 = SA[r], a1 = SB[r];
            float4 dv = dd[i4], xv = xd[i4];
            xv.x = a0 * dv.x + a1 * xv.x;
            xv.y = a0 * dv.y + a1 * xv.y;
            xv.z = a0 * dv.z + a1 * xv.z;
            xv.w = a0 * dv.w + a1 * xv.w;
            xd[i4] = xv;
        }
    }
    __syncthreads();

    // ---- S6a: mLA = z_m @ Wv_m -> Ms (m no longer needed) ----
    load_w(Wv_m, Ws);
    __syncthreads();
    {
        float acc[4][8] = {{0.f}};
        gemm64(X1m, Ws, rbase, cbase, acc);
        __syncthreads();  // everyone done reading Ms before overwrite
#pragma unroll
        for (int i = 0; i < 4; ++i)
#pragma unroll
            for (int j = 0; j < 8; ++j)
                Ms[(rbase + i) * CDIM + cbase + j] = acc[i][j];
    }
    __syncthreads();

    // ---- S6b: ne = (z_d @ Wv_d) * mLA -> Ds ----
    load_w(Wv_d, Ws);
    __syncthreads();
    {
        float acc[4][8] = {{0.f}};
        gemm64(X1d, Ws, rbase, cbase, acc);
        __syncthreads();  // everyone done reading Ds before overwrite
#pragma unroll
        for (int i = 0; i < 4; ++i)
#pragma unroll
            for (int j = 0; j < 8; ++j) {
                int idx = (rbase + i) * CDIM + cbase + j;
                Ds[idx] = acc[i][j] * Ms[idx];
            }
    }
    __syncthreads();

    // ---- S7: pre = relu(ne @ W1) . W2 ; out = sigmoid(pre) ----
    load_w(W1, Ws);
    __syncthreads();
    {
        float acc[4][8] = {{0.f}};
        gemm64(Ds, Ws, rbase, cbase, acc);
#pragma unroll
        for (int i = 0; i < 4; ++i) {
            float q = 0.f;
#pragma unroll
            for (int j = 0; j < 8; ++j)
                q = fmaf(fmaxf(acc[i][j], 0.f), SW2[cbase + j], q);
            R0[(rbase + i) * 16 + cg] = q;
        }
    }
    __syncthreads();
    if (tid < BT) {
        float pre = 0.f;
#pragma unroll
        for (int g = 0; g < 16; ++g) pre += R0[tid * 16 + g];
        out[b0 + tid] = 1.f / (1.f + expf(-pre));
    }
}

extern "C" void kernel_launch(void* const* d_in, const int* in_sizes, int n_in,
                              void* d_out, int out_size) {
    const float* em    = (const float*)d_in[0];
    const float* ed    = (const float*)d_in[1];
    const float* Wgcn  = (const float*)d_in[2];
    const float* Wq_m  = (const float*)d_in[3];
    const float* Wk_m  = (const float*)d_in[4];
    const float* Wv_m  = (const float*)d_in[5];
    const float* Wq_d  = (const float*)d_in[6];
    const float* Wk_d  = (const float*)d_in[7];
    const float* Wv_d  = (const float*)d_in[8];
    const float* W1    = (const float*)d_in[9];
    const float* W2    = (const float*)d_in[10];
    float* out = (float*)d_out;

    cudaFuncSetAttribute(mdi_kernel, cudaFuncAttributeMaxDynamicSharedMemorySize, SMEM_BYTES);

    int B = out_size;                // 262144
    prep_kernel<<<256, 128>>>(Wq_m, Wk_m, Wq_d, Wk_d);
    mdi_kernel<<<B / BT, NTHREADS, SMEM_BYTES>>>(em, ed, Wgcn, Wv_m, Wv_d, W1, W2, out);
}

// round 5
// speedup vs baseline: 2.2738x; 2.2738x over previous
#include <cuda_runtime.h>
#include <cuda_bf16.h>
#include <cstdint>
#include <math.h>

#define CDIM 128
#define BT   64
#define LDA  132            // fp32 row stride (conflict-free)
#define LDW  136            // bf16 weight row stride (272B, conflict-free + 16B aligned)
#define NTHREADS 256
#define EPSF 1e-8f
#define WSLOT_BYTES (CDIM * LDW * 2)      // 34816 per hi/lo component

// Weight images, pre-split bf16 hi/lo, stored as B[n][k] = W[k][n] (padded).
// slots: 0=Wgcn 1=gM0(Wq_m@Wk_m^T) 2=gM1 3=Wv_m 4=Wv_d 5=W1
__device__ __align__(16) __nv_bfloat16 g_Wpad[6][2][CDIM * LDW];

// ---------------- helpers ----------------
__device__ __forceinline__ uint32_t smem_u32(const void* p) {
    uint32_t a;
    asm("{ .reg .u64 t; cvta.to.shared.u64 t, %1; cvt.u32.u64 %0, t; }" : "=r"(a) : "l"(p));
    return a;
}
__device__ __forceinline__ void split2(float a, float b, uint32_t& hw, uint32_t& lw) {
    __nv_bfloat162 h = __floats2bfloat162_rn(a, b);
    hw = *reinterpret_cast<uint32_t*>(&h);
    float la = a - __bfloat162float(h.x);
    float lb = b - __bfloat162float(h.y);
    __nv_bfloat162 l = __floats2bfloat162_rn(la, lb);
    lw = *reinterpret_cast<uint32_t*>(&l);
}
__device__ __forceinline__ void mma_bf16(float c[4], const uint32_t a[4], uint32_t b0, uint32_t b1) {
    asm volatile("mma.sync.aligned.m16n8k16.row.col.f32.bf16.bf16.f32 "
        "{%0,%1,%2,%3}, {%4,%5,%6,%7}, {%8,%9}, {%0,%1,%2,%3};"
        : "+f"(c[0]), "+f"(c[1]), "+f"(c[2]), "+f"(c[3])
        : "r"(a[0]), "r"(a[1]), "r"(a[2]), "r"(a[3]), "r"(b0), "r"(b1));
}
#define LDSM4(r0_, r1_, r2_, r3_, addr) asm volatile( \
    "ldmatrix.sync.aligned.m8n8.x4.shared.b16 {%0,%1,%2,%3}, [%4];" \
    : "=r"(r0_), "=r"(r1_), "=r"(r2_), "=r"(r3_) : "r"(addr))

// ---------------- prep kernels ----------------
__device__ __forceinline__ void store_w(int slot, int n, int k, float v) {
    __nv_bfloat16 h = __float2bfloat16_rn(v);
    __nv_bfloat16 l = __float2bfloat16_rn(v - __bfloat162float(h));
    g_Wpad[slot][0][n * LDW + k] = h;
    g_Wpad[slot][1][n * LDW + k] = l;
}
__global__ void prep_plain(const float* __restrict__ Wgcn, const float* __restrict__ Wvm,
                           const float* __restrict__ Wvd,  const float* __restrict__ W1) {
    const float* W; int slot;
    switch (blockIdx.x) {
        case 0:  W = Wgcn; slot = 0; break;
        case 1:  W = Wvm;  slot = 3; break;
        case 2:  W = Wvd;  slot = 4; break;
        default: W = W1;   slot = 5; break;
    }
    for (int e = threadIdx.x; e < CDIM * CDIM; e += blockDim.x) {
        int n = e >> 7, k = e & 127;
        store_w(slot, n, k, W[k * CDIM + n]);
    }
}
__global__ void prep_gm(const float* __restrict__ Wq_m, const float* __restrict__ Wk_m,
                        const float* __restrict__ Wq_d, const float* __restrict__ Wk_d) {
    __shared__ float krow[CDIM];
    int which = blockIdx.x >> 7;
    int n = blockIdx.x & 127;
    const float* Wq = which ? Wq_d : Wq_m;
    const float* Wk = which ? Wk_d : Wk_m;
    if (threadIdx.x < CDIM) krow[threadIdx.x] = Wk[n * CDIM + threadIdx.x];
    __syncthreads();
    int k = threadIdx.x;
    const float4* q4 = reinterpret_cast<const float4*>(Wq + k * CDIM);
    float s = 0.f;
#pragma unroll
    for (int c4 = 0; c4 < CDIM / 4; ++c4) {
        float4 q = q4[c4];
        s = fmaf(q.x, krow[c4 * 4 + 0], s);
        s = fmaf(q.y, krow[c4 * 4 + 1], s);
        s = fmaf(q.z, krow[c4 * 4 + 2], s);
        s = fmaf(q.w, krow[c4 * 4 + 3], s);
    }
    store_w(which ? 2 : 1, n, k, s);
}

// ---------------- SMEM layout (floats unless noted) ----------------
#define F_MS   0
#define F_DS   (BT * LDA)            // 8448
#define F_X1M  (2 * BT * LDA)
#define F_X1D  (3 * BT * LDA)
#define WS_OFF_BYTES (4 * BT * LDA * 4)          // 135168
#define F_R0   ((WS_OFF_BYTES + 2 * WSLOT_BYTES) / 4)   // 51200
#define F_R1   (F_R0 + 512)
#define F_SA   (F_R1 + 512)
#define F_SB   (F_SA + 64)
#define F_SW2  (F_SB + 64)
#define SMEM_BYTES ((F_SW2 + 128) * 4)           // 209920

__device__ __forceinline__ void load_wimg(int slot, char* ws) {
    const uint4* g = reinterpret_cast<const uint4*>(g_Wpad[slot][0]);
    uint4* s = reinterpret_cast<uint4*>(ws);
    for (int i = threadIdx.x; i < (2 * WSLOT_BYTES) / 16; i += NTHREADS) s[i] = g[i];
}

// GEMM stage: acc[8][4] += split3( A[64x128] ) @ Wimg^T  for this warp's tile.
// COMB=1: A row r = ca(r)*Xa[r] + cb(r)*Xb[r].
template<int COMB>
__device__ __forceinline__ void gemm_tc(const float* __restrict__ Xa, const float* __restrict__ Xb,
                                        float ca0, float cb0, float ca1, float cb1,
                                        uint32_t whA, int r0, int cK, float acc[8][4]) {
    const float* pa0 = Xa + r0 * LDA;
    const float* pa1 = Xa + (r0 + 8) * LDA;
    const float* pb0 = Xb + r0 * LDA;
    const float* pb1 = Xb + (r0 + 8) * LDA;
#pragma unroll 1
    for (int ks = 0; ks < 8; ++ks) {
        int c0 = ks * 16 + cK;
        uint32_t ah[4], al[4];
        {
            float2 v0 = *reinterpret_cast<const float2*>(pa0 + c0);
            float2 v1 = *reinterpret_cast<const float2*>(pa1 + c0);
            float2 v2 = *reinterpret_cast<const float2*>(pa0 + c0 + 8);
            float2 v3 = *reinterpret_cast<const float2*>(pa1 + c0 + 8);
            if (COMB) {
                float2 u0 = *reinterpret_cast<const float2*>(pb0 + c0);
                float2 u1 = *reinterpret_cast<const float2*>(pb1 + c0);
                float2 u2 = *reinterpret_cast<const float2*>(pb0 + c0 + 8);
                float2 u3 = *reinterpret_cast<const float2*>(pb1 + c0 + 8);
                v0.x = ca0 * v0.x + cb0 * u0.x;  v0.y = ca0 * v0.y + cb0 * u0.y;
                v1.x = ca1 * v1.x + cb1 * u1.x;  v1.y = ca1 * v1.y + cb1 * u1.y;
                v2.x = ca0 * v2.x + cb0 * u2.x;  v2.y = ca0 * v2.y + cb0 * u2.y;
                v3.x = ca1 * v3.x + cb1 * u3.x;  v3.y = ca1 * v3.y + cb1 * u3.y;
            }
            split2(v0.x, v0.y, ah[0], al[0]);
            split2(v1.x, v1.y, ah[1], al[1]);
            split2(v2.x, v2.y, ah[2], al[2]);
            split2(v3.x, v3.y, ah[3], al[3]);
        }
#pragma unroll
        for (int np = 0; np < 4; ++np) {
            uint32_t off = (uint32_t)(np * (16 * 2 * LDW) + ks * 32);
            uint32_t bh0, bh1, bh2, bh3, bl0, bl1, bl2, bl3;
            LDSM4(bh0, bh1, bh2, bh3, whA + off);
            LDSM4(bl0, bl1, bl2, bl3, whA + (uint32_t)WSLOT_BYTES + off);
            mma_bf16(acc[np * 2],     ah, bh0, bh1);
            mma_bf16(acc[np * 2],     ah, bl0, bl1);
            mma_bf16(acc[np * 2],     al, bh0, bh1);
            mma_bf16(acc[np * 2 + 1], ah, bh2, bh3);
            mma_bf16(acc[np * 2 + 1], ah, bl2, bl3);
            mma_bf16(acc[np * 2 + 1], al, bh2, bh3);
        }
    }
}

__global__ __launch_bounds__(NTHREADS, 1)
void mdi_mma_kernel(const float* __restrict__ em, const float* __restrict__ ed,
                    const float* __restrict__ W2, float* __restrict__ out) {
    extern __shared__ float sh[];
    float* Ms  = sh + F_MS;
    float* Ds  = sh + F_DS;
    float* X1m = sh + F_X1M;
    float* X1d = sh + F_X1D;
    char*  Ws  = reinterpret_cast<char*>(sh) + WS_OFF_BYTES;
    float* R0  = sh + F_R0;
    float* R1  = sh + F_R1;
    float* SA  = sh + F_SA;
    float* SB  = sh + F_SB;
    float* SW2 = sh + F_SW2;

    const int tid  = threadIdx.x;
    const int w    = tid >> 5;
    const int lane = tid & 31;
    const int mb    = (w & 3) * 16;          // warp m-tile base row
    const int nbase = (w >> 2) * 64;         // warp n-half base col
    const int r0    = mb + (lane >> 2);      // lane row (and r0+8)
    const int cK    = 2 * (lane & 3);        // lane col within 8-wide tile
    const int half4 = (w >> 2) * 4;
    const int lq    = lane & 3;
    const int b0 = blockIdx.x * BT;
    const float ISQRTC = 0.0883883476483184f;

    // per-lane ldmatrix B address offset (within a 16-row n-pair block)
    const uint32_t ws_u = smem_u32(Ws);
    const int n_lane = (lane & 7) + ((lane & 16) ? 8 : 0);
    const uint32_t whA = ws_u + (uint32_t)((nbase + n_lane) * (2 * LDW) + ((lane >> 3) & 1) * 16);

    // ---- load inputs (padded), W2, Wgcn image ----
    {
        const float4* gm = reinterpret_cast<const float4*>(em + (size_t)b0 * CDIM);
        const float4* gd = reinterpret_cast<const float4*>(ed + (size_t)b0 * CDIM);
        for (int i = tid; i < BT * 32; i += NTHREADS) {
            int row = i >> 5, c = i & 31;
            *reinterpret_cast<float4*>(&Ms[row * LDA + c * 4]) = gm[i];
            *reinterpret_cast<float4*>(&Ds[row * LDA + c * 4]) = gd[i];
        }
        if (tid < CDIM) SW2[tid] = W2[tid];
    }
    load_wimg(0, Ws);
    __syncthreads();

    // ---- per-batch scalars -> SA (diag a), SB (offdiag b) ----
    {
        int rr = tid >> 2, part = tid & 3;
        const float* mr = Ms + rr * LDA;
        const float* dr = Ds + rr * LDA;
        float dman = 0.f, sm2 = 0.f, sd2 = 0.f, md = 0.f;
        int k0 = part * 32;
#pragma unroll
        for (int k = 0; k < 32; k += 4) {
            float4 mv = *reinterpret_cast<const float4*>(mr + k0 + k);
            float4 dv = *reinterpret_cast<const float4*>(dr + k0 + k);
            dman += fabsf(mv.x - dv.x) + fabsf(mv.y - dv.y) + fabsf(mv.z - dv.z) + fabsf(mv.w - dv.w);
            sm2 += mv.x * mv.x + mv.y * mv.y + mv.z * mv.z + mv.w * mv.w;
            sd2 += dv.x * dv.x + dv.y * dv.y + dv.z * dv.z + dv.w * dv.w;
            md  += mv.x * dv.x + mv.y * dv.y + mv.z * dv.z + mv.w * dv.w;
        }
        R0[rr * 4 + part] = dman;
        R0[256 + rr * 4 + part] = sm2;
        R1[rr * 4 + part] = sd2;
        R1[256 + rr * 4 + part] = md;
    }
    __syncthreads();
    if (tid < BT) {
        int b4 = tid * 4;
        float dman = R0[b4] + R0[b4 + 1] + R0[b4 + 2] + R0[b4 + 3];
        float sm2  = R0[256 + b4] + R0[257 + b4] + R0[258 + b4] + R0[259 + b4];
        float sd2  = R1[b4] + R1[b4 + 1] + R1[b4 + 2] + R1[b4 + 3];
        float md   = R1[256 + b4] + R1[257 + b4] + R1[258 + b4] + R1[259 + b4];
        float s3 = 1.f / (1.f + dman);
        float c = md / (sqrtf(sm2 + EPSF) * sqrtf(sd2 + EPSF));
        if (c < 0.f) c *= 0.01f;
        float s1 = 1.f / (1.f + c);
        SA[tid] = fminf(s3, s1);
        SB[tid] = fminf(dman * s3, c * s1);
    }
    __syncthreads();

    // ===== stage 1: x1m = relu((a*m+b*d)@Wgcn) + m =====
    {
        float acc[8][4] = {};
        gemm_tc<1>(Ms, Ds, SA[r0], SB[r0], SA[r0 + 8], SB[r0 + 8], whA, r0, cK, acc);
#pragma unroll
        for (int nt = 0; nt < 8; ++nt) {
            int col = nbase + nt * 8 + cK;
            float2 s0 = *reinterpret_cast<const float2*>(&Ms[r0 * LDA + col]);
            float2 s1 = *reinterpret_cast<const float2*>(&Ms[(r0 + 8) * LDA + col]);
            *reinterpret_cast<float2*>(&X1m[r0 * LDA + col]) =
                make_float2(fmaxf(acc[nt][0], 0.f) + s0.x, fmaxf(acc[nt][1], 0.f) + s0.y);
            *reinterpret_cast<float2*>(&X1m[(r0 + 8) * LDA + col]) =
                make_float2(fmaxf(acc[nt][2], 0.f) + s1.x, fmaxf(acc[nt][3], 0.f) + s1.y);
        }
    }
    // ===== stage 2: x1d = relu((b*m+a*d)@Wgcn) + d =====
    {
        float acc[8][4] = {};
        gemm_tc<1>(Ms, Ds, SB[r0], SA[r0], SB[r0 + 8], SA[r0 + 8], whA, r0, cK, acc);
#pragma unroll
        for (int nt = 0; nt < 8; ++nt) {
            int col = nbase + nt * 8 + cK;
            float2 s0 = *reinterpret_cast<const float2*>(&Ds[r0 * LDA + col]);
            float2 s1 = *reinterpret_cast<const float2*>(&Ds[(r0 + 8) * LDA + col]);
            *reinterpret_cast<float2*>(&X1d[r0 * LDA + col]) =
                make_float2(fmaxf(acc[nt][0], 0.f) + s0.x, fmaxf(acc[nt][1], 0.f) + s0.y);
            *reinterpret_cast<float2*>(&X1d[(r0 + 8) * LDA + col]) =
                make_float2(fmaxf(acc[nt][2], 0.f) + s1.x, fmaxf(acc[nt][3], 0.f) + s1.y);
        }
    }
    __syncthreads();
    load_wimg(1, Ws);   // gM0
    __syncthreads();

    // ===== stages 3/4: attention per branch =====
#pragma unroll 1
    for (int br = 0; br < 2; ++br) {
        float* X1 = br ? X1d : X1m;
        float* X0 = br ? Ds : Ms;
        float acc[8][4] = {};
        gemm_tc<0>(X1, X1, 0.f, 0.f, 0.f, 0.f, whA, r0, cK, acc);
        // score partials: q0 = t.x0, q1 = t.x1
        {
            float q00 = 0.f, q10 = 0.f, q01 = 0.f, q11 = 0.f;
#pragma unroll
            for (int nt = 0; nt < 8; ++nt) {
                int col = nbase + nt * 8 + cK;
                float2 a0 = *reinterpret_cast<const float2*>(&X0[r0 * LDA + col]);
                float2 a1 = *reinterpret_cast<const float2*>(&X1[r0 * LDA + col]);
                float2 b0v = *reinterpret_cast<const float2*>(&X0[(r0 + 8) * LDA + col]);
                float2 b1v = *reinterpret_cast<const float2*>(&X1[(r0 + 8) * LDA + col]);
                q00 += acc[nt][0] * a0.x + acc[nt][1] * a0.y;
                q10 += acc[nt][0] * a1.x + acc[nt][1] * a1.y;
                q01 += acc[nt][2] * b0v.x + acc[nt][3] * b0v.y;
                q11 += acc[nt][2] * b1v.x + acc[nt][3] * b1v.y;
            }
            R0[r0 * 8 + half4 + lq] = q00;
            R1[r0 * 8 + half4 + lq] = q10;
            R0[(r0 + 8) * 8 + half4 + lq] = q01;
            R1[(r0 + 8) * 8 + half4 + lq] = q11;
        }
        __syncthreads();
        load_wimg(br ? 3 : 2, Ws);   // prefetch next W (gM1 then Wv_m)
        if (tid < BT) {
            float s0 = 0.f, s1v = 0.f;
#pragma unroll
            for (int g = 0; g < 8; ++g) { s0 += R0[tid * 8 + g]; s1v += R1[tid * 8 + g]; }
            s0 *= ISQRTC; s1v *= ISQRTC;
            float mx = fmaxf(s0, s1v);
            float e0 = expf(s0 - mx), e1 = expf(s1v - mx);
            float inv = 1.f / (e0 + e1);
            SA[tid] = e0 * inv;
            SB[tid] = e1 * inv;
        }
        __syncthreads();
        // z = a0*x0 + a1*x1 -> X1
        for (int i = tid; i < BT * 32; i += NTHREADS) {
            int row = i >> 5, c = i & 31;
            float a0 = SA[row], a1 = SB[row];
            float4 xv = *reinterpret_cast<const float4*>(&X1[row * LDA + c * 4]);
            float4 mv = *reinterpret_cast<const float4*>(&X0[row * LDA + c * 4]);
            xv.x = a0 * mv.x + a1 * xv.x;
            xv.y = a0 * mv.y + a1 * xv.y;
            xv.z = a0 * mv.z + a1 * xv.z;
            xv.w = a0 * mv.w + a1 * xv.w;
            *reinterpret_cast<float4*>(&X1[row * LDA + c * 4]) = xv;
        }
        __syncthreads();
    }

    // ===== stage 5: mLA = z_m @ Wv_m (kept in registers) =====
    float mla[8][4] = {};
    gemm_tc<0>(X1m, X1m, 0.f, 0.f, 0.f, 0.f, whA, r0, cK, mla);
    __syncthreads();
    load_wimg(4, Ws);   // Wv_d
    __syncthreads();

    // ===== stage 6: ne = (z_d @ Wv_d) * mLA -> Ds =====
    {
        float acc[8][4] = {};
        gemm_tc<0>(X1d, X1d, 0.f, 0.f, 0.f, 0.f, whA, r0, cK, acc);
#pragma unroll
        for (int nt = 0; nt < 8; ++nt) {
            int col = nbase + nt * 8 + cK;
            *reinterpret_cast<float2*>(&Ds[r0 * LDA + col]) =
                make_float2(acc[nt][0] * mla[nt][0], acc[nt][1] * mla[nt][1]);
            *reinterpret_cast<float2*>(&Ds[(r0 + 8) * LDA + col]) =
                make_float2(acc[nt][2] * mla[nt][2], acc[nt][3] * mla[nt][3]);
        }
    }
    __syncthreads();
    load_wimg(5, Ws);   // W1
    __syncthreads();

    // ===== stage 7: pre = relu(ne @ W1) . W2 ; out = sigmoid =====
    {
        float acc[8][4] = {};
        gemm_tc<0>(Ds, Ds, 0.f, 0.f, 0.f, 0.f, whA, r0, cK, acc);
        float p0 = 0.f, p1 = 0.f;
#pragma unroll
        for (int nt = 0; nt < 8; ++nt) {
            int col = nbase + nt * 8 + cK;
            p0 += fmaxf(acc[nt][0], 0.f) * SW2[col] + fmaxf(acc[nt][1], 0.f) * SW2[col + 1];
            p1 += fmaxf(acc[nt][2], 0.f) * SW2[col] + fmaxf(acc[nt][3], 0.f) * SW2[col + 1];
        }
        R0[r0 * 8 + half4 + lq] = p0;
        R0[(r0 + 8) * 8 + half4 + lq] = p1;
    }
    __syncthreads();
    if (tid < BT) {
        float pre = 0.f;
#pragma unroll
        for (int g = 0; g < 8; ++g) pre += R0[tid * 8 + g];
        out[b0 + tid] = 1.f / (1.f + expf(-pre));
    }
}

extern "C" void kernel_launch(void* const* d_in, const int* in_sizes, int n_in,
                              void* d_out, int out_size) {
    const float* em    = (const float*)d_in[0];
    const float* ed    = (const float*)d_in[1];
    const float* Wgcn  = (const float*)d_in[2];
    const float* Wq_m  = (const float*)d_in[3];
    const float* Wk_m  = (const float*)d_in[4];
    const float* Wv_m  = (const float*)d_in[5];
    const float* Wq_d  = (const float*)d_in[6];
    const float* Wk_d  = (const float*)d_in[7];
    const float* Wv_d  = (const float*)d_in[8];
    const float* W1    = (const float*)d_in[9];
    const float* W2    = (const float*)d_in[10];
    float* out = (float*)d_out;

    cudaFuncSetAttribute(mdi_mma_kernel, cudaFuncAttributeMaxDynamicSharedMemorySize, SMEM_BYTES);

    int B = out_size;   // 262144
    prep_plain<<<4, 256>>>(Wgcn, Wv_m, Wv_d, W1);
    prep_gm<<<256, 128>>>(Wq_m, Wk_m, Wq_d, Wk_d);
    mdi_mma_kernel<<<B / BT, NTHREADS, SMEM_BYTES>>>(em, ed, W2, out);
}

// round 6
// speedup vs baseline: 3.3394x; 1.4686x over previous
#include <cuda_runtime.h>
#include <cuda_bf16.h>
#include <cstdint>
#include <math.h>

#define CDIM 128
#define BT   64
#define LDA  132            // fp32 row stride (conflict-free)
#define LDW  136            // bf16 weight row stride (272B, conflict-free, 16B aligned)
#define NTHREADS 256
#define EPSF 1e-8f
#define WCOMP_BYTES (CDIM * LDW * 2)   // 34816 per hi/lo component
#define WCHUNKS (WCOMP_BYTES / 16)     // 2176

// Weight images, pre-split bf16 hi/lo components, stored as B[n][k] = W[k][n].
// slots: 0=Wgcn 1=gM0(Wq_m@Wk_m^T/sqrtC) 2=gM1 3=Wv_m 4=Wv_d 5=W1
__device__ __align__(16) __nv_bfloat16 g_Wpad[6][2][CDIM * LDW];

// ---------------- helpers ----------------
__device__ __forceinline__ uint32_t smem_u32(const void* p) {
    uint32_t a;
    asm("{ .reg .u64 t; cvta.to.shared.u64 t, %1; cvt.u32.u64 %0, t; }" : "=r"(a) : "l"(p));
    return a;
}
__device__ __forceinline__ void split2(float a, float b, uint32_t& hw, uint32_t& lw) {
    __nv_bfloat162 h = __floats2bfloat162_rn(a, b);
    hw = *reinterpret_cast<uint32_t*>(&h);
    float la = a - __bfloat162float(h.x);
    float lb = b - __bfloat162float(h.y);
    __nv_bfloat162 l = __floats2bfloat162_rn(la, lb);
    lw = *reinterpret_cast<uint32_t*>(&l);
}
__device__ __forceinline__ void mma_bf16(float c[4], const uint32_t a[4], uint32_t b0, uint32_t b1) {
    asm volatile("mma.sync.aligned.m16n8k16.row.col.f32.bf16.bf16.f32 "
        "{%0,%1,%2,%3}, {%4,%5,%6,%7}, {%8,%9}, {%0,%1,%2,%3};"
        : "+f"(c[0]), "+f"(c[1]), "+f"(c[2]), "+f"(c[3])
        : "r"(a[0]), "r"(a[1]), "r"(a[2]), "r"(a[3]), "r"(b0), "r"(b1));
}
#define LDSM4(r0_, r1_, r2_, r3_, addr) asm volatile( \
    "ldmatrix.sync.aligned.m8n8.x4.shared.b16 {%0,%1,%2,%3}, [%4];" \
    : "=r"(r0_), "=r"(r1_), "=r"(r2_), "=r"(r3_) : "r"(addr))

#define CPA16(s, g)   asm volatile("cp.async.cg.shared.global [%0], [%1], 16;" :: "r"(s), "l"(g))
#define CPA_COMMIT()  asm volatile("cp.async.commit_group;" ::: "memory")
#define CPA_WAIT(n)   asm volatile("cp.async.wait_group %0;" :: "n"(n) : "memory")

__device__ __forceinline__ void cpa_load(const __nv_bfloat16* g, uint32_t s_base) {
    const char* gp = reinterpret_cast<const char*>(g);
    for (int i = threadIdx.x; i < WCHUNKS; i += NTHREADS)
        CPA16(s_base + (uint32_t)(i * 16), gp + (size_t)i * 16);
    CPA_COMMIT();
}

// ---------------- prep kernels ----------------
__device__ __forceinline__ void store_w(int slot, int n, int k, float v) {
    __nv_bfloat16 h = __float2bfloat16_rn(v);
    __nv_bfloat16 l = __float2bfloat16_rn(v - __bfloat162float(h));
    g_Wpad[slot][0][n * LDW + k] = h;
    g_Wpad[slot][1][n * LDW + k] = l;
}
__global__ void prep_plain(const float* __restrict__ Wgcn, const float* __restrict__ Wvm,
                           const float* __restrict__ Wvd,  const float* __restrict__ W1) {
    const float* W; int slot;
    switch (blockIdx.x) {
        case 0:  W = Wgcn; slot = 0; break;
        case 1:  W = Wvm;  slot = 3; break;
        case 2:  W = Wvd;  slot = 4; break;
        default: W = W1;   slot = 5; break;
    }
    for (int e = threadIdx.x; e < CDIM * CDIM; e += blockDim.x) {
        int n = e >> 7, k = e & 127;
        store_w(slot, n, k, W[k * CDIM + n]);
    }
}
__global__ void prep_gm(const float* __restrict__ Wq_m, const float* __restrict__ Wk_m,
                        const float* __restrict__ Wq_d, const float* __restrict__ Wk_d) {
    __shared__ float krow[CDIM];
    int which = blockIdx.x >> 7;
    int n = blockIdx.x & 127;
    const float* Wq = which ? Wq_d : Wq_m;
    const float* Wk = which ? Wk_d : Wk_m;
    if (threadIdx.x < CDIM) krow[threadIdx.x] = Wk[n * CDIM + threadIdx.x];
    __syncthreads();
    int k = threadIdx.x;
    const float4* q4 = reinterpret_cast<const float4*>(Wq + k * CDIM);
    float s = 0.f;
#pragma unroll
    for (int c4 = 0; c4 < CDIM / 4; ++c4) {
        float4 q = q4[c4];
        s = fmaf(q.x, krow[c4 * 4 + 0], s);
        s = fmaf(q.y, krow[c4 * 4 + 1], s);
        s = fmaf(q.z, krow[c4 * 4 + 2], s);
        s = fmaf(q.w, krow[c4 * 4 + 3], s);
    }
    // fold 1/sqrt(C) into the score matrix
    store_w(which ? 2 : 1, n, k, s * 0.0883883476483184f);
}

// ---------------- SMEM layout ----------------
#define F_MS   0
#define F_DS   (BT * LDA)
#define F_X1M  (2 * BT * LDA)
#define F_X1D  (3 * BT * LDA)
#define WSH_BYTES (4 * BT * LDA * 4)                 // 135168
#define WSL_BYTES (WSH_BYTES + WCOMP_BYTES)          // 169984
#define F_R0   ((WSL_BYTES + WCOMP_BYTES) / 4)       // 51200
#define F_R1   (F_R0 + 512)
#define F_SAM  (F_R1 + 512)
#define F_SBM  (F_SAM + 64)
#define F_SAD  (F_SBM + 64)
#define F_SBD  (F_SAD + 64)
#define F_SW2  (F_SBD + 64)
#define SMEM_BYTES ((F_SW2 + 128) * 4)               // 210432

// ---------------- GEMM passes ----------------
// pass A: build A-fragments (optionally a per-row linear comb of Xa,Xb), keep hi
// fragments in ah[], do acc += ah@Whi + al@Whi.
template<int COMB>
__device__ __forceinline__ void passA(const float* __restrict__ Xa, const float* __restrict__ Xb,
                                      float ca0, float cb0, float ca1, float cb1,
                                      uint32_t whi, int r0, int cK,
                                      float acc[8][4], uint32_t ah[8][4]) {
    const float* pa0 = Xa + r0 * LDA;
    const float* pa1 = Xa + (r0 + 8) * LDA;
    const float* pb0 = Xb + r0 * LDA;
    const float* pb1 = Xb + (r0 + 8) * LDA;
#pragma unroll
    for (int ks = 0; ks < 8; ++ks) {
        int c0 = ks * 16 + cK;
        uint32_t al[4];
        {
            float2 v0 = *reinterpret_cast<const float2*>(pa0 + c0);
            float2 v1 = *reinterpret_cast<const float2*>(pa1 + c0);
            float2 v2 = *reinterpret_cast<const float2*>(pa0 + c0 + 8);
            float2 v3 = *reinterpret_cast<const float2*>(pa1 + c0 + 8);
            if (COMB) {
                float2 u0 = *reinterpret_cast<const float2*>(pb0 + c0);
                float2 u1 = *reinterpret_cast<const float2*>(pb1 + c0);
                float2 u2 = *reinterpret_cast<const float2*>(pb0 + c0 + 8);
                float2 u3 = *reinterpret_cast<const float2*>(pb1 + c0 + 8);
                v0.x = ca0 * v0.x + cb0 * u0.x;  v0.y = ca0 * v0.y + cb0 * u0.y;
                v1.x = ca1 * v1.x + cb1 * u1.x;  v1.y = ca1 * v1.y + cb1 * u1.y;
                v2.x = ca0 * v2.x + cb0 * u2.x;  v2.y = ca0 * v2.y + cb0 * u2.y;
                v3.x = ca1 * v3.x + cb1 * u3.x;  v3.y = ca1 * v3.y + cb1 * u3.y;
            }
            split2(v0.x, v0.y, ah[ks][0], al[0]);
            split2(v1.x, v1.y, ah[ks][1], al[1]);
            split2(v2.x, v2.y, ah[ks][2], al[2]);
            split2(v3.x, v3.y, ah[ks][3], al[3]);
        }
#pragma unroll
        for (int np = 0; np < 4; ++np) {
            uint32_t off = (uint32_t)(np * (16 * 2 * LDW) + ks * 32);
            uint32_t b0_, b1_, b2_, b3_;
            LDSM4(b0_, b1_, b2_, b3_, whi + off);
            mma_bf16(acc[np * 2],     ah[ks], b0_, b1_);
            mma_bf16(acc[np * 2],     al,     b0_, b1_);
            mma_bf16(acc[np * 2 + 1], ah[ks], b2_, b3_);
            mma_bf16(acc[np * 2 + 1], al,     b2_, b3_);
        }
    }
}
// pass B: acc += ah@Wlo using the kept hi fragments.
__device__ __forceinline__ void passB(uint32_t wlo, const uint32_t ah[8][4], float acc[8][4]) {
#pragma unroll
    for (int ks = 0; ks < 8; ++ks)
#pragma unroll
        for (int np = 0; np < 4; ++np) {
            uint32_t off = (uint32_t)(np * (16 * 2 * LDW) + ks * 32);
            uint32_t b0_, b1_, b2_, b3_;
            LDSM4(b0_, b1_, b2_, b3_, wlo + off);
            mma_bf16(acc[np * 2],     ah[ks], b0_, b1_);
            mma_bf16(acc[np * 2 + 1], ah[ks], b2_, b3_);
        }
}

__global__ __launch_bounds__(NTHREADS, 1)
void mdi_mma_kernel(const float* __restrict__ em, const float* __restrict__ ed,
                    const float* __restrict__ W2, float* __restrict__ out) {
    extern __shared__ float sh[];
    float* Ms  = sh + F_MS;
    float* Ds  = sh + F_DS;
    float* X1m = sh + F_X1M;
    float* X1d = sh + F_X1D;
    uint32_t wsh_u = smem_u32(reinterpret_cast<char*>(sh) + WSH_BYTES);
    uint32_t wsl_u = smem_u32(reinterpret_cast<char*>(sh) + WSL_BYTES);
    float* R0  = sh + F_R0;
    float* R1  = sh + F_R1;
    float* SAm = sh + F_SAM;
    float* SBm = sh + F_SBM;
    float* SAd = sh + F_SAD;
    float* SBd = sh + F_SBD;
    float* SW2 = sh + F_SW2;

    const int tid  = threadIdx.x;
    const int w    = tid >> 5;
    const int lane = tid & 31;
    const int mb    = (w & 3) * 16;
    const int nbase = (w >> 2) * 64;
    const int r0    = mb + (lane >> 2);
    const int cK    = 2 * (lane & 3);
    const int half4 = (w >> 2) * 4;
    const int lq    = lane & 3;
    const int b0 = blockIdx.x * BT;

    const int n_lane = (lane & 7) + ((lane & 16) ? 8 : 0);
    const uint32_t laneoff = (uint32_t)((nbase + n_lane) * (2 * LDW) + ((lane >> 3) & 1) * 16);
    const uint32_t whi = wsh_u + laneoff;
    const uint32_t wlo = wsl_u + laneoff;

    // kick off Wgcn prefetch immediately (G0 hi, G1 lo)
    cpa_load(g_Wpad[0][0], wsh_u);
    cpa_load(g_Wpad[0][1], wsl_u);

    // ---- load inputs (padded) + W2 ----
    {
        const float4* gm = reinterpret_cast<const float4*>(em + (size_t)b0 * CDIM);
        const float4* gd = reinterpret_cast<const float4*>(ed + (size_t)b0 * CDIM);
        for (int i = tid; i < BT * 32; i += NTHREADS) {
            int row = i >> 5, c = i & 31;
            *reinterpret_cast<float4*>(&Ms[row * LDA + c * 4]) = gm[i];
            *reinterpret_cast<float4*>(&Ds[row * LDA + c * 4]) = gd[i];
        }
        if (tid < CDIM) SW2[tid] = W2[tid];
    }
    __syncthreads();

    // ---- per-batch scalars -> SAm (diag a), SBm (offdiag b) ----
    {
        int rr = tid >> 2, part = tid & 3;
        const float* mr = Ms + rr * LDA;
        const float* dr = Ds + rr * LDA;
        float dman = 0.f, sm2 = 0.f, sd2 = 0.f, md = 0.f;
        int k0 = part * 32;
#pragma unroll
        for (int k = 0; k < 32; k += 4) {
            float4 mv = *reinterpret_cast<const float4*>(mr + k0 + k);
            float4 dv = *reinterpret_cast<const float4*>(dr + k0 + k);
            dman += fabsf(mv.x - dv.x) + fabsf(mv.y - dv.y) + fabsf(mv.z - dv.z) + fabsf(mv.w - dv.w);
            sm2 += mv.x * mv.x + mv.y * mv.y + mv.z * mv.z + mv.w * mv.w;
            sd2 += dv.x * dv.x + dv.y * dv.y + dv.z * dv.z + dv.w * dv.w;
            md  += mv.x * dv.x + mv.y * dv.y + mv.z * dv.z + mv.w * dv.w;
        }
        R0[rr * 4 + part] = dman;
        R0[256 + rr * 4 + part] = sm2;
        R1[rr * 4 + part] = sd2;
        R1[256 + rr * 4 + part] = md;
    }
    __syncthreads();
    if (tid < BT) {
        int b4 = tid * 4;
        float dman = R0[b4] + R0[b4 + 1] + R0[b4 + 2] + R0[b4 + 3];
        float sm2  = R0[256 + b4] + R0[257 + b4] + R0[258 + b4] + R0[259 + b4];
        float sd2  = R1[b4] + R1[b4 + 1] + R1[b4 + 2] + R1[b4 + 3];
        float md   = R1[256 + b4] + R1[257 + b4] + R1[258 + b4] + R1[259 + b4];
        float s3 = 1.f / (1.f + dman);
        float c = md / (sqrtf(sm2 + EPSF) * sqrtf(sd2 + EPSF));
        if (c < 0.f) c *= 0.01f;
        float s1 = 1.f / (1.f + c);
        SAm[tid] = fminf(s3, s1);
        SBm[tid] = fminf(dman * s3, c * s1);
    }
    __syncthreads();

    uint32_t ah[8][4];

    // ===== stage 1: x1m = relu((a*m+b*d)@Wgcn) + m =====
    CPA_WAIT(1); __syncthreads();
    {
        float acc[8][4] = {};
        passA<1>(Ms, Ds, SAm[r0], SBm[r0], SAm[r0 + 8], SBm[r0 + 8], whi, r0, cK, acc, ah);
        CPA_WAIT(0); __syncthreads();
        passB(wlo, ah, acc);
#pragma unroll
        for (int nt = 0; nt < 8; ++nt) {
            int col = nbase + nt * 8 + cK;
            float2 s0 = *reinterpret_cast<const float2*>(&Ms[r0 * LDA + col]);
            float2 s1 = *reinterpret_cast<const float2*>(&Ms[(r0 + 8) * LDA + col]);
            *reinterpret_cast<float2*>(&X1m[r0 * LDA + col]) =
                make_float2(fmaxf(acc[nt][0], 0.f) + s0.x, fmaxf(acc[nt][1], 0.f) + s0.y);
            *reinterpret_cast<float2*>(&X1m[(r0 + 8) * LDA + col]) =
                make_float2(fmaxf(acc[nt][2], 0.f) + s1.x, fmaxf(acc[nt][3], 0.f) + s1.y);
        }
    }
    // ===== stage 2: x1d = relu((b*m+a*d)@Wgcn) + d =====
    {
        float acc[8][4] = {};
        passA<1>(Ms, Ds, SBm[r0], SAm[r0], SBm[r0 + 8], SAm[r0 + 8], whi, r0, cK, acc, ah);
        __syncthreads();
        cpa_load(g_Wpad[1][0], wsh_u);      // G2: gM0.hi
        passB(wlo, ah, acc);
        __syncthreads();
        cpa_load(g_Wpad[1][1], wsl_u);      // G3: gM0.lo
#pragma unroll
        for (int nt = 0; nt < 8; ++nt) {
            int col = nbase + nt * 8 + cK;
            float2 s0 = *reinterpret_cast<const float2*>(&Ds[r0 * LDA + col]);
            float2 s1 = *reinterpret_cast<const float2*>(&Ds[(r0 + 8) * LDA + col]);
            *reinterpret_cast<float2*>(&X1d[r0 * LDA + col]) =
                make_float2(fmaxf(acc[nt][0], 0.f) + s0.x, fmaxf(acc[nt][1], 0.f) + s0.y);
            *reinterpret_cast<float2*>(&X1d[(r0 + 8) * LDA + col]) =
                make_float2(fmaxf(acc[nt][2], 0.f) + s1.x, fmaxf(acc[nt][3], 0.f) + s1.y);
        }
    }

    // ===== stages 3/4: attention scores per branch (scale folded into gM) =====
#pragma unroll 1
    for (int br = 0; br < 2; ++br) {
        float* X1 = br ? X1d : X1m;
        float* X0 = br ? Ds : Ms;
        float acc[8][4] = {};
        CPA_WAIT(1); __syncthreads();
        passA<0>(X1, X1, 0.f, 0.f, 0.f, 0.f, whi, r0, cK, acc, ah);
        __syncthreads();
        cpa_load(g_Wpad[br ? 3 : 2][0], wsh_u);   // G4 / G6: next hi
        CPA_WAIT(1); __syncthreads();
        passB(wlo, ah, acc);
        __syncthreads();
        cpa_load(g_Wpad[br ? 3 : 2][1], wsl_u);   // G5 / G7: next lo
        // score partials: s0 = t.x0, s1 = t.x1
        {
            float q00 = 0.f, q10 = 0.f, q01 = 0.f, q11 = 0.f;
#pragma unroll
            for (int nt = 0; nt < 8; ++nt) {
                int col = nbase + nt * 8 + cK;
                float2 a0 = *reinterpret_cast<const float2*>(&X0[r0 * LDA + col]);
                float2 a1 = *reinterpret_cast<const float2*>(&X1[r0 * LDA + col]);
                float2 c0 = *reinterpret_cast<const float2*>(&X0[(r0 + 8) * LDA + col]);
                float2 c1 = *reinterpret_cast<const float2*>(&X1[(r0 + 8) * LDA + col]);
                q00 += acc[nt][0] * a0.x + acc[nt][1] * a0.y;
                q10 += acc[nt][0] * a1.x + acc[nt][1] * a1.y;
                q01 += acc[nt][2] * c0.x + acc[nt][3] * c0.y;
                q11 += acc[nt][2] * c1.x + acc[nt][3] * c1.y;
            }
            R0[r0 * 8 + half4 + lq] = q00;
            R1[r0 * 8 + half4 + lq] = q10;
            R0[(r0 + 8) * 8 + half4 + lq] = q01;
            R1[(r0 + 8) * 8 + half4 + lq] = q11;
        }
        __syncthreads();
        if (tid < BT) {
            float s0 = 0.f, s1v = 0.f;
#pragma unroll
            for (int g = 0; g < 8; ++g) { s0 += R0[tid * 8 + g]; s1v += R1[tid * 8 + g]; }
            float mx = fmaxf(s0, s1v);
            float e0 = expf(s0 - mx), e1 = expf(s1v - mx);
            float inv = 1.f / (e0 + e1);
            if (br == 0) { SAm[tid] = e0 * inv; SBm[tid] = e1 * inv; }
            else         { SAd[tid] = e0 * inv; SBd[tid] = e1 * inv; }
        }
    }

    // ===== stage 5: mLA = (a0m*x0m + a1m*x1m) @ Wv_m, kept in registers =====
    float mla[8][4] = {};
    CPA_WAIT(1); __syncthreads();
    passA<1>(Ms, X1m, SAm[r0], SBm[r0], SAm[r0 + 8], SBm[r0 + 8], whi, r0, cK, mla, ah);
    __syncthreads();
    cpa_load(g_Wpad[4][0], wsh_u);              // G8: Wv_d.hi
    CPA_WAIT(1); __syncthreads();
    passB(wlo, ah, mla);
    __syncthreads();
    cpa_load(g_Wpad[4][1], wsl_u);              // G9: Wv_d.lo

    // ===== stage 6: ne = ((a0d*x0d + a1d*x1d) @ Wv_d) * mLA -> X1m =====
    {
        float acc[8][4] = {};
        CPA_WAIT(1); __syncthreads();
        passA<1>(Ds, X1d, SAd[r0], SBd[r0], SAd[r0 + 8], SBd[r0 + 8], whi, r0, cK, acc, ah);
        __syncthreads();
        cpa_load(g_Wpad[5][0], wsh_u);          // G10: W1.hi
        CPA_WAIT(1); __syncthreads();
        passB(wlo, ah, acc);
        __syncthreads();
        cpa_load(g_Wpad[5][1], wsl_u);          // G11: W1.lo
#pragma unroll
        for (int nt = 0; nt < 8; ++nt) {
            int col = nbase + nt * 8 + cK;
            *reinterpret_cast<float2*>(&X1m[r0 * LDA + col]) =
                make_float2(acc[nt][0] * mla[nt][0], acc[nt][1] * mla[nt][1]);
            *reinterpret_cast<float2*>(&X1m[(r0 + 8) * LDA + col]) =
                make_float2(acc[nt][2] * mla[nt][2], acc[nt][3] * mla[nt][3]);
        }
    }

    // ===== stage 7: pre = relu(ne @ W1) . W2 ; out = sigmoid =====
    {
        float acc[8][4] = {};
        CPA_WAIT(1); __syncthreads();
        passA<0>(X1m, X1m, 0.f, 0.f, 0.f, 0.f, whi, r0, cK, acc, ah);
        CPA_WAIT(0); __syncthreads();
        passB(wlo, ah, acc);
        float p0 = 0.f, p1 = 0.f;
#pragma unroll
        for (int nt = 0; nt < 8; ++nt) {
            int col = nbase + nt * 8 + cK;
            p0 += fmaxf(acc[nt][0], 0.f) * SW2[col] + fmaxf(acc[nt][1], 0.f) * SW2[col + 1];
            p1 += fmaxf(acc[nt][2], 0.f) * SW2[col] + fmaxf(acc[nt][3], 0.f) * SW2[col + 1];
        }
        R0[r0 * 8 + half4 + lq] = p0;
        R0[(r0 + 8) * 8 + half4 + lq] = p1;
    }
    __syncthreads();
    if (tid < BT) {
        float pre = 0.f;
#pragma unroll
        for (int g = 0; g < 8; ++g) pre += R0[tid * 8 + g];
        out[b0 + tid] = 1.f / (1.f + expf(-pre));
    }
}

extern "C" void kernel_launch(void* const* d_in, const int* in_sizes, int n_in,
                              void* d_out, int out_size) {
    const float* em    = (const float*)d_in[0];
    const float* ed    = (const float*)d_in[1];
    const float* Wgcn  = (const float*)d_in[2];
    const float* Wq_m  = (const float*)d_in[3];
    const float* Wk_m  = (const float*)d_in[4];
    const float* Wv_m  = (const float*)d_in[5];
    const float* Wq_d  = (const float*)d_in[6];
    const float* Wk_d  = (const float*)d_in[7];
    const float* Wv_d  = (const float*)d_in[8];
    const float* W1    = (const float*)d_in[9];
    const float* W2    = (const float*)d_in[10];
    float* out = (float*)d_out;

    cudaFuncSetAttribute(mdi_mma_kernel, cudaFuncAttributeMaxDynamicSharedMemorySize, SMEM_BYTES);

    int B = out_size;   // 262144
    prep_plain<<<4, 256>>>(Wgcn, Wv_m, Wv_d, W1);
    prep_gm<<<256, 128>>>(Wq_m, Wk_m, Wq_d, Wk_d);
    mdi_mma_kernel<<<B / BT, NTHREADS, SMEM_BYTES>>>(em, ed, W2, out);
}

// round 7
// speedup vs baseline: 4.3827x; 1.3124x over previous
#include <cuda_runtime.h>
#include <cuda_fp16.h>
#include <cstdint>
#include <math.h>

#define CDIM 128
#define BT   64
#define LDA  132            // fp32 row stride (conflict-free)
#define LDW  136            // fp16 weight row stride (272B, conflict-free, 16B aligned)
#define NTHREADS 256
#define EPSF 1e-8f
#define WCOMP_BYTES (CDIM * LDW * 2)   // 34816 bytes per weight image (single fp16 comp)
#define WCHUNKS (WCOMP_BYTES / 16)     // 2176

// Weight images, fp16, stored as B[n][k] = W[k][n] (padded rows).
// slots: 0=Wgcn 1=gM0(Wq_m@Wk_m^T/sqrtC) 2=gM1 3=Wv_m 4=Wv_d 5=W1
__device__ __align__(16) __half g_Wpad[6][CDIM * LDW];

// ---------------- helpers ----------------
__device__ __forceinline__ uint32_t smem_u32(const void* p) {
    uint32_t a;
    asm("{ .reg .u64 t; cvta.to.shared.u64 t, %1; cvt.u32.u64 %0, t; }" : "=r"(a) : "l"(p));
    return a;
}
// split x into fp16 hi + fp16 lo (packed pairs)
__device__ __forceinline__ void split2h(float a, float b, uint32_t& hw, uint32_t& lw) {
    __half2 h = __floats2half2_rn(a, b);
    hw = *reinterpret_cast<uint32_t*>(&h);
    float2 hf = __half22float2(h);
    __half2 l = __floats2half2_rn(a - hf.x, b - hf.y);
    lw = *reinterpret_cast<uint32_t*>(&l);
}
__device__ __forceinline__ void mma_f16(float c[4], const uint32_t a[4], uint32_t b0, uint32_t b1) {
    asm volatile("mma.sync.aligned.m16n8k16.row.col.f32.f16.f16.f32 "
        "{%0,%1,%2,%3}, {%4,%5,%6,%7}, {%8,%9}, {%0,%1,%2,%3};"
        : "+f"(c[0]), "+f"(c[1]), "+f"(c[2]), "+f"(c[3])
        : "r"(a[0]), "r"(a[1]), "r"(a[2]), "r"(a[3]), "r"(b0), "r"(b1));
}
#define LDSM4(r0_, r1_, r2_, r3_, addr) asm volatile( \
    "ldmatrix.sync.aligned.m8n8.x4.shared.b16 {%0,%1,%2,%3}, [%4];" \
    : "=r"(r0_), "=r"(r1_), "=r"(r2_), "=r"(r3_) : "r"(addr))

#define CPA16(s, g)   asm volatile("cp.async.cg.shared.global [%0], [%1], 16;" :: "r"(s), "l"(g))
#define CPA_COMMIT()  asm volatile("cp.async.commit_group;" ::: "memory")
#define CPA_WAIT(n)   asm volatile("cp.async.wait_group %0;" :: "n"(n) : "memory")

__device__ __forceinline__ void cpa_load(const __half* g, uint32_t s_base) {
    const char* gp = reinterpret_cast<const char*>(g);
    for (int i = threadIdx.x; i < WCHUNKS; i += NTHREADS)
        CPA16(s_base + (uint32_t)(i * 16), gp + (size_t)i * 16);
    CPA_COMMIT();
}

// ---------------- prep kernels ----------------
__global__ void prep_plain(const float* __restrict__ Wgcn, const float* __restrict__ Wvm,
                           const float* __restrict__ Wvd,  const float* __restrict__ W1) {
    // 64 blocks: slot = bid>>4, slice = bid&15 (1024 elems each)
    int slot4 = blockIdx.x >> 4;
    const float* W; int slot;
    switch (slot4) {
        case 0:  W = Wgcn; slot = 0; break;
        case 1:  W = Wvm;  slot = 3; break;
        case 2:  W = Wvd;  slot = 4; break;
        default: W = W1;   slot = 5; break;
    }
    int e0 = (blockIdx.x & 15) * 1024;
    for (int e = e0 + threadIdx.x; e < e0 + 1024; e += blockDim.x) {
        int n = e >> 7, k = e & 127;
        g_Wpad[slot][n * LDW + k] = __float2half_rn(W[k * CDIM + n]);
    }
}
__global__ void prep_gm(const float* __restrict__ Wq_m, const float* __restrict__ Wk_m,
                        const float* __restrict__ Wq_d, const float* __restrict__ Wk_d) {
    __shared__ float krow[CDIM];
    int which = blockIdx.x >> 7;
    int n = blockIdx.x & 127;
    const float* Wq = which ? Wq_d : Wq_m;
    const float* Wk = which ? Wk_d : Wk_m;
    if (threadIdx.x < CDIM) krow[threadIdx.x] = Wk[n * CDIM + threadIdx.x];
    __syncthreads();
    int k = threadIdx.x;
    const float4* q4 = reinterpret_cast<const float4*>(Wq + k * CDIM);
    float s = 0.f;
#pragma unroll
    for (int c4 = 0; c4 < CDIM / 4; ++c4) {
        float4 q = q4[c4];
        s = fmaf(q.x, krow[c4 * 4 + 0], s);
        s = fmaf(q.y, krow[c4 * 4 + 1], s);
        s = fmaf(q.z, krow[c4 * 4 + 2], s);
        s = fmaf(q.w, krow[c4 * 4 + 3], s);
    }
    // fold 1/sqrt(C) into the score matrices
    g_Wpad[which ? 2 : 1][n * LDW + k] = __float2half_rn(s * 0.0883883476483184f);
}

// ---------------- SMEM layout ----------------
#define F_MS   0
#define F_DS   (BT * LDA)
#define F_X1M  (2 * BT * LDA)
#define F_X1D  (3 * BT * LDA)
#define WB0_BYTES (4 * BT * LDA * 4)                 // 135168
#define WB1_BYTES (WB0_BYTES + WCOMP_BYTES)          // 169984
#define F_R0   ((WB1_BYTES + WCOMP_BYTES) / 4)       // 51200
#define F_R1   (F_R0 + 512)
#define F_SAM  (F_R1 + 512)
#define F_SBM  (F_SAM + 64)
#define F_SAD  (F_SBM + 64)
#define F_SBD  (F_SAD + 64)
#define F_SW2  (F_SBD + 64)
#define SMEM_BYTES ((F_SW2 + 128) * 4)               // 210432

// ---------------- GEMM passes (2-term fp16: acc += (xh+xl)@W) ----------------
template<int COMB>
__device__ __forceinline__ void gemm_f16(const float* __restrict__ Xa, const float* __restrict__ Xb,
                                         float ca0, float cb0, float ca1, float cb1,
                                         uint32_t wb, int r0, int cK, float acc[8][4]) {
    const float* pa0 = Xa + r0 * LDA;
    const float* pa1 = Xa + (r0 + 8) * LDA;
    const float* pb0 = Xb + r0 * LDA;
    const float* pb1 = Xb + (r0 + 8) * LDA;
#pragma unroll
    for (int ks = 0; ks < 8; ++ks) {
        int c0 = ks * 16 + cK;
        uint32_t ah[4], al[4];
        {
            float2 v0 = *reinterpret_cast<const float2*>(pa0 + c0);
            float2 v1 = *reinterpret_cast<const float2*>(pa1 + c0);
            float2 v2 = *reinterpret_cast<const float2*>(pa0 + c0 + 8);
            float2 v3 = *reinterpret_cast<const float2*>(pa1 + c0 + 8);
            if (COMB) {
                float2 u0 = *reinterpret_cast<const float2*>(pb0 + c0);
                float2 u1 = *reinterpret_cast<const float2*>(pb1 + c0);
                float2 u2 = *reinterpret_cast<const float2*>(pb0 + c0 + 8);
                float2 u3 = *reinterpret_cast<const float2*>(pb1 + c0 + 8);
                v0.x = ca0 * v0.x + cb0 * u0.x;  v0.y = ca0 * v0.y + cb0 * u0.y;
                v1.x = ca1 * v1.x + cb1 * u1.x;  v1.y = ca1 * v1.y + cb1 * u1.y;
                v2.x = ca0 * v2.x + cb0 * u2.x;  v2.y = ca0 * v2.y + cb0 * u2.y;
                v3.x = ca1 * v3.x + cb1 * u3.x;  v3.y = ca1 * v3.y + cb1 * u3.y;
            }
            split2h(v0.x, v0.y, ah[0], al[0]);
            split2h(v1.x, v1.y, ah[1], al[1]);
            split2h(v2.x, v2.y, ah[2], al[2]);
            split2h(v3.x, v3.y, ah[3], al[3]);
        }
#pragma unroll
        for (int np = 0; np < 4; ++np) {
            uint32_t off = (uint32_t)(np * (16 * 2 * LDW) + ks * 32);
            uint32_t b0_, b1_, b2_, b3_;
            LDSM4(b0_, b1_, b2_, b3_, wb + off);
            mma_f16(acc[np * 2],     ah, b0_, b1_);
            mma_f16(acc[np * 2],     al, b0_, b1_);
            mma_f16(acc[np * 2 + 1], ah, b2_, b3_);
            mma_f16(acc[np * 2 + 1], al, b2_, b3_);
        }
    }
}

// merged GCN pass: u0 = a*m + b*d, u1 = b*m + a*d share loads and B fragments.
__device__ __forceinline__ void gemm_f16_dual(const float* __restrict__ Ms, const float* __restrict__ Ds,
                                              float a0, float b0c, float a1, float b1c,
                                              uint32_t wb, int r0, int cK,
                                              float acc0[8][4], float acc1[8][4]) {
    const float* pm0 = Ms + r0 * LDA;
    const float* pm1 = Ms + (r0 + 8) * LDA;
    const float* pd0 = Ds + r0 * LDA;
    const float* pd1 = Ds + (r0 + 8) * LDA;
#pragma unroll
    for (int ks = 0; ks < 8; ++ks) {
        int c0 = ks * 16 + cK;
        uint32_t ah0[4], al0[4], ah1[4], al1[4];
        {
            float2 m0 = *reinterpret_cast<const float2*>(pm0 + c0);
            float2 m1 = *reinterpret_cast<const float2*>(pm1 + c0);
            float2 m2 = *reinterpret_cast<const float2*>(pm0 + c0 + 8);
            float2 m3 = *reinterpret_cast<const float2*>(pm1 + c0 + 8);
            float2 d0 = *reinterpret_cast<const float2*>(pd0 + c0);
            float2 d1 = *reinterpret_cast<const float2*>(pd1 + c0);
            float2 d2 = *reinterpret_cast<const float2*>(pd0 + c0 + 8);
            float2 d3 = *reinterpret_cast<const float2*>(pd1 + c0 + 8);
            split2h(a0 * m0.x + b0c * d0.x, a0 * m0.y + b0c * d0.y, ah0[0], al0[0]);
            split2h(a1 * m1.x + b1c * d1.x, a1 * m1.y + b1c * d1.y, ah0[1], al0[1]);
            split2h(a0 * m2.x + b0c * d2.x, a0 * m2.y + b0c * d2.y, ah0[2], al0[2]);
            split2h(a1 * m3.x + b1c * d3.x, a1 * m3.y + b1c * d3.y, ah0[3], al0[3]);
            split2h(b0c * m0.x + a0 * d0.x, b0c * m0.y + a0 * d0.y, ah1[0], al1[0]);
            split2h(b1c * m1.x + a1 * d1.x, b1c * m1.y + a1 * d1.y, ah1[1], al1[1]);
            split2h(b0c * m2.x + a0 * d2.x, b0c * m2.y + a0 * d2.y, ah1[2], al1[2]);
            split2h(b1c * m3.x + a1 * d3.x, b1c * m3.y + a1 * d3.y, ah1[3], al1[3]);
        }
#pragma unroll
        for (int np = 0; np < 4; ++np) {
            uint32_t off = (uint32_t)(np * (16 * 2 * LDW) + ks * 32);
            uint32_t b0_, b1_, b2_, b3_;
            LDSM4(b0_, b1_, b2_, b3_, wb + off);
            mma_f16(acc0[np * 2],     ah0, b0_, b1_);
            mma_f16(acc0[np * 2],     al0, b0_, b1_);
            mma_f16(acc0[np * 2 + 1], ah0, b2_, b3_);
            mma_f16(acc0[np * 2 + 1], al0, b2_, b3_);
            mma_f16(acc1[np * 2],     ah1, b0_, b1_);
            mma_f16(acc1[np * 2],     al1, b0_, b1_);
            mma_f16(acc1[np * 2 + 1], ah1, b2_, b3_);
            mma_f16(acc1[np * 2 + 1], al1, b2_, b3_);
        }
    }
}

__global__ __launch_bounds__(NTHREADS, 1)
void mdi_mma_kernel(const float* __restrict__ em, const float* __restrict__ ed,
                    const float* __restrict__ W2, float* __restrict__ out) {
    extern __shared__ float sh[];
    float* Ms  = sh + F_MS;
    float* Ds  = sh + F_DS;
    float* X1m = sh + F_X1M;
    float* X1d = sh + F_X1D;
    uint32_t wb0_u = smem_u32(reinterpret_cast<char*>(sh) + WB0_BYTES);
    uint32_t wb1_u = smem_u32(reinterpret_cast<char*>(sh) + WB1_BYTES);
    float* R0  = sh + F_R0;
    float* R1  = sh + F_R1;
    float* SAm = sh + F_SAM;
    float* SBm = sh + F_SBM;
    float* SAd = sh + F_SAD;
    float* SBd = sh + F_SBD;
    float* SW2 = sh + F_SW2;

    const int tid  = threadIdx.x;
    const int w    = tid >> 5;
    const int lane = tid & 31;
    const int mb    = (w & 3) * 16;
    const int nbase = (w >> 2) * 64;
    const int r0    = mb + (lane >> 2);
    const int cK    = 2 * (lane & 3);
    const int half4 = (w >> 2) * 4;
    const int lq    = lane & 3;
    const int b0 = blockIdx.x * BT;

    const int n_lane = (lane & 7) + ((lane & 16) ? 8 : 0);
    const uint32_t laneoff = (uint32_t)((nbase + n_lane) * (2 * LDW) + ((lane >> 3) & 1) * 16);
    const uint32_t wb0 = wb0_u + laneoff;
    const uint32_t wb1 = wb1_u + laneoff;

    // prefetch W0 (Wgcn) -> B0, W1 (gM0) -> B1
    cpa_load(g_Wpad[0], wb0_u);
    cpa_load(g_Wpad[1], wb1_u);

    // ---- load inputs (padded) + W2 ----
    {
        const float4* gm = reinterpret_cast<const float4*>(em + (size_t)b0 * CDIM);
        const float4* gd = reinterpret_cast<const float4*>(ed + (size_t)b0 * CDIM);
        for (int i = tid; i < BT * 32; i += NTHREADS) {
            int row = i >> 5, c = i & 31;
            *reinterpret_cast<float4*>(&Ms[row * LDA + c * 4]) = gm[i];
            *reinterpret_cast<float4*>(&Ds[row * LDA + c * 4]) = gd[i];
        }
        if (tid < CDIM) SW2[tid] = W2[tid];
    }
    __syncthreads();

    // ---- per-batch scalars -> SAm (diag a), SBm (offdiag b) ----
    {
        int rr = tid >> 2, part = tid & 3;
        const float* mr = Ms + rr * LDA;
        const float* dr = Ds + rr * LDA;
        float dman = 0.f, sm2 = 0.f, sd2 = 0.f, md = 0.f;
        int k0 = part * 32;
#pragma unroll
        for (int k = 0; k < 32; k += 4) {
            float4 mv = *reinterpret_cast<const float4*>(mr + k0 + k);
            float4 dv = *reinterpret_cast<const float4*>(dr + k0 + k);
            dman += fabsf(mv.x - dv.x) + fabsf(mv.y - dv.y) + fabsf(mv.z - dv.z) + fabsf(mv.w - dv.w);
            sm2 += mv.x * mv.x + mv.y * mv.y + mv.z * mv.z + mv.w * mv.w;
            sd2 += dv.x * dv.x + dv.y * dv.y + dv.z * dv.z + dv.w * dv.w;
            md  += mv.x * dv.x + mv.y * dv.y + mv.z * dv.z + mv.w * dv.w;
        }
        R0[rr * 4 + part] = dman;
        R0[256 + rr * 4 + part] = sm2;
        R1[rr * 4 + part] = sd2;
        R1[256 + rr * 4 + part] = md;
    }
    __syncthreads();
    if (tid < BT) {
        int b4 = tid * 4;
        float dman = R0[b4] + R0[b4 + 1] + R0[b4 + 2] + R0[b4 + 3];
        float sm2  = R0[256 + b4] + R0[257 + b4] + R0[258 + b4] + R0[259 + b4];
        float sd2  = R1[b4] + R1[b4 + 1] + R1[b4 + 2] + R1[b4 + 3];
        float md   = R1[256 + b4] + R1[257 + b4] + R1[258 + b4] + R1[259 + b4];
        float s3 = 1.f / (1.f + dman);
        float c = md / (sqrtf(sm2 + EPSF) * sqrtf(sd2 + EPSF));
        if (c < 0.f) c *= 0.01f;
        float s1 = 1.f / (1.f + c);
        SAm[tid] = fminf(s3, s1);
        SBm[tid] = fminf(dman * s3, c * s1);
    }
    __syncthreads();

    // ===== pass 0 (merged GCN): x1m/x1d = relu(u @ Wgcn) + x0 =====
    CPA_WAIT(1); __syncthreads();        // W0 ready (W1 outstanding)
    {
        float acc0[8][4] = {}, acc1[8][4] = {};
        gemm_f16_dual(Ms, Ds, SAm[r0], SBm[r0], SAm[r0 + 8], SBm[r0 + 8],
                      wb0, r0, cK, acc0, acc1);
        __syncthreads();
        cpa_load(g_Wpad[2], wb0_u);      // W2 = gM1 -> B0
#pragma unroll
        for (int nt = 0; nt < 8; ++nt) {
            int col = nbase + nt * 8 + cK;
            float2 m0 = *reinterpret_cast<const float2*>(&Ms[r0 * LDA + col]);
            float2 m1 = *reinterpret_cast<const float2*>(&Ms[(r0 + 8) * LDA + col]);
            float2 d0 = *reinterpret_cast<const float2*>(&Ds[r0 * LDA + col]);
            float2 d1 = *reinterpret_cast<const float2*>(&Ds[(r0 + 8) * LDA + col]);
            *reinterpret_cast<float2*>(&X1m[r0 * LDA + col]) =
                make_float2(fmaxf(acc0[nt][0], 0.f) + m0.x, fmaxf(acc0[nt][1], 0.f) + m0.y);
            *reinterpret_cast<float2*>(&X1m[(r0 + 8) * LDA + col]) =
                make_float2(fmaxf(acc0[nt][2], 0.f) + m1.x, fmaxf(acc0[nt][3], 0.f) + m1.y);
            *reinterpret_cast<float2*>(&X1d[r0 * LDA + col]) =
                make_float2(fmaxf(acc1[nt][0], 0.f) + d0.x, fmaxf(acc1[nt][1], 0.f) + d0.y);
            *reinterpret_cast<float2*>(&X1d[(r0 + 8) * LDA + col]) =
                make_float2(fmaxf(acc1[nt][2], 0.f) + d1.x, fmaxf(acc1[nt][3], 0.f) + d1.y);
        }
    }

    // ===== passes 1/2: attention scores per branch (scale folded into gM) =====
#pragma unroll 1
    for (int br = 0; br < 2; ++br) {
        float* X1 = br ? X1d : X1m;
        float* X0 = br ? Ds : Ms;
        uint32_t wb = br ? wb0 : wb1;    // gM0 in B1, gM1 in B0
        float acc[8][4] = {};
        CPA_WAIT(1); __syncthreads();    // current gM ready
        gemm_f16<0>(X1, X1, 0.f, 0.f, 0.f, 0.f, wb, r0, cK, acc);
        __syncthreads();
        cpa_load(g_Wpad[br ? 4 : 3], br ? wb0_u : wb1_u);   // Wv_m -> B1, Wv_d -> B0
        // score partials
        {
            float q00 = 0.f, q10 = 0.f, q01 = 0.f, q11 = 0.f;
#pragma unroll
            for (int nt = 0; nt < 8; ++nt) {
                int col = nbase + nt * 8 + cK;
                float2 a0 = *reinterpret_cast<const float2*>(&X0[r0 * LDA + col]);
                float2 a1 = *reinterpret_cast<const float2*>(&X1[r0 * LDA + col]);
                float2 c0 = *reinterpret_cast<const float2*>(&X0[(r0 + 8) * LDA + col]);
                float2 c1 = *reinterpret_cast<const float2*>(&X1[(r0 + 8) * LDA + col]);
                q00 += acc[nt][0] * a0.x + acc[nt][1] * a0.y;
                q10 += acc[nt][0] * a1.x + acc[nt][1] * a1.y;
                q01 += acc[nt][2] * c0.x + acc[nt][3] * c0.y;
                q11 += acc[nt][2] * c1.x + acc[nt][3] * c1.y;
            }
            R0[r0 * 8 + half4 + lq] = q00;
            R1[r0 * 8 + half4 + lq] = q10;
            R0[(r0 + 8) * 8 + half4 + lq] = q01;
            R1[(r0 + 8) * 8 + half4 + lq] = q11;
        }
        __syncthreads();
        if (tid < BT) {
            float s0 = 0.f, s1v = 0.f;
#pragma unroll
            for (int g = 0; g < 8; ++g) { s0 += R0[tid * 8 + g]; s1v += R1[tid * 8 + g]; }
            float mx = fmaxf(s0, s1v);
            float e0 = __expf(s0 - mx), e1 = __expf(s1v - mx);
            float inv = 1.f / (e0 + e1);
            if (br == 0) { SAm[tid] = e0 * inv; SBm[tid] = e1 * inv; }
            else         { SAd[tid] = e0 * inv; SBd[tid] = e1 * inv; }
        }
    }

    // ===== pass 3: mLA = (a0m*x0m + a1m*x1m) @ Wv_m, kept in registers =====
    float mla[8][4] = {};
    CPA_WAIT(1); __syncthreads();        // Wv_m (B1) ready
    gemm_f16<1>(Ms, X1m, SAm[r0], SBm[r0], SAm[r0 + 8], SBm[r0 + 8], wb1, r0, cK, mla);
    __syncthreads();
    cpa_load(g_Wpad[5], wb1_u);          // W1 -> B1

    // ===== pass 4: ne = ((a0d*x0d + a1d*x1d) @ Wv_d) * mLA -> X1m =====
    {
        float acc[8][4] = {};
        CPA_WAIT(1); __syncthreads();    // Wv_d (B0) ready
        gemm_f16<1>(Ds, X1d, SAd[r0], SBd[r0], SAd[r0 + 8], SBd[r0 + 8], wb0, r0, cK, acc);
#pragma unroll
        for (int nt = 0; nt < 8; ++nt) {
            int col = nbase + nt * 8 + cK;
            *reinterpret_cast<float2*>(&X1m[r0 * LDA + col]) =
                make_float2(acc[nt][0] * mla[nt][0], acc[nt][1] * mla[nt][1]);
            *reinterpret_cast<float2*>(&X1m[(r0 + 8) * LDA + col]) =
                make_float2(acc[nt][2] * mla[nt][2], acc[nt][3] * mla[nt][3]);
        }
    }

    // ===== pass 5: pre = relu(ne @ W1) . W2 ; out = sigmoid =====
    {
        float acc[8][4] = {};
        CPA_WAIT(0); __syncthreads();    // W1 (B1) ready; also orders ne writes
        gemm_f16<0>(X1m, X1m, 0.f, 0.f, 0.f, 0.f, wb1, r0, cK, acc);
        float p0 = 0.f, p1 = 0.f;
#pragma unroll
        for (int nt = 0; nt < 8; ++nt) {
            int col = nbase + nt * 8 + cK;
            p0 += fmaxf(acc[nt][0], 0.f) * SW2[col] + fmaxf(acc[nt][1], 0.f) * SW2[col + 1];
            p1 += fmaxf(acc[nt][2], 0.f) * SW2[col] + fmaxf(acc[nt][3], 0.f) * SW2[col + 1];
        }
        R0[r0 * 8 + half4 + lq] = p0;
        R0[(r0 + 8) * 8 + half4 + lq] = p1;
    }
    __syncthreads();
    if (tid < BT) {
        float pre = 0.f;
#pragma unroll
        for (int g = 0; g < 8; ++g) pre += R0[tid * 8 + g];
        out[b0 + tid] = 1.f / (1.f + __expf(-pre));
    }
}

extern "C" void kernel_launch(void* const* d_in, const int* in_sizes, int n_in,
                              void* d_out, int out_size) {
    const float* em    = (const float*)d_in[0];
    const float* ed    = (const float*)d_in[1];
    const float* Wgcn  = (const float*)d_in[2];
    const float* Wq_m  = (const float*)d_in[3];
    const float* Wk_m  = (const float*)d_in[4];
    const float* Wv_m  = (const float*)d_in[5];
    const float* Wq_d  = (const float*)d_in[6];
    const float* Wk_d  = (const float*)d_in[7];
    const float* Wv_d  = (const float*)d_in[8];
    const float* W1    = (const float*)d_in[9];
    const float* W2    = (const float*)d_in[10];
    float* out = (float*)d_out;

    cudaFuncSetAttribute(mdi_mma_kernel, cudaFuncAttributeMaxDynamicSharedMemorySize, SMEM_BYTES);

    int B = out_size;   // 262144
    prep_plain<<<64, 256>>>(Wgcn, Wv_m, Wv_d, W1);
    prep_gm<<<256, 128>>>(Wq_m, Wk_m, Wq_d, Wk_d);
    mdi_mma_kernel<<<B / BT, NTHREADS, SMEM_BYTES>>>(em, ed, W2, out);
}

// round 8
// speedup vs baseline: 4.7917x; 1.0933x over previous
#include <cuda_runtime.h>
#include <cuda_fp16.h>
#include <cstdint>
#include <math.h>

#define CDIM 128
#define BT   64
#define LDA  132            // fp32 row stride (conflict-free)
#define LDW  136            // fp16 weight row stride (272B, conflict-free, 16B aligned)
#define NTHREADS 256
#define EPSF 1e-8f
#define WCOMP_BYTES (CDIM * LDW * 2)   // 34816 bytes per weight image
#define WCHUNKS (WCOMP_BYTES / 16)     // 2176

// Weight images, fp16, stored as B[n][k] = W[k][n] (padded rows).
// slots: 0=Wgcn 1=gM0(Wq_m@Wk_m^T/sqrtC) 2=gM1 3=Wv_m 4=Wv_d 5=W1
__device__ __align__(16) __half g_Wpad[6][CDIM * LDW];

// ---------------- helpers ----------------
__device__ __forceinline__ uint32_t smem_u32(const void* p) {
    uint32_t a;
    asm("{ .reg .u64 t; cvta.to.shared.u64 t, %1; cvt.u32.u64 %0, t; }" : "=r"(a) : "l"(p));
    return a;
}
__device__ __forceinline__ uint32_t cvt2h(float a, float b) {
    __half2 h = __floats2half2_rn(a, b);
    return *reinterpret_cast<uint32_t*>(&h);
}
__device__ __forceinline__ void mma_f16(float c[4], const uint32_t a[4], uint32_t b0, uint32_t b1) {
    asm volatile("mma.sync.aligned.m16n8k16.row.col.f32.f16.f16.f32 "
        "{%0,%1,%2,%3}, {%4,%5,%6,%7}, {%8,%9}, {%0,%1,%2,%3};"
        : "+f"(c[0]), "+f"(c[1]), "+f"(c[2]), "+f"(c[3])
        : "r"(a[0]), "r"(a[1]), "r"(a[2]), "r"(a[3]), "r"(b0), "r"(b1));
}
#define LDSM4(r0_, r1_, r2_, r3_, addr) asm volatile( \
    "ldmatrix.sync.aligned.m8n8.x4.shared.b16 {%0,%1,%2,%3}, [%4];" \
    : "=r"(r0_), "=r"(r1_), "=r"(r2_), "=r"(r3_) : "r"(addr))

#define CPA16(s, g)   asm volatile("cp.async.cg.shared.global [%0], [%1], 16;" :: "r"(s), "l"(g))
#define CPA_COMMIT()  asm volatile("cp.async.commit_group;" ::: "memory")
#define CPA_WAIT(n)   asm volatile("cp.async.wait_group %0;" :: "n"(n) : "memory")

__device__ __forceinline__ void cpa_load(const __half* g, uint32_t s_base) {
    const char* gp = reinterpret_cast<const char*>(g);
    for (int i = threadIdx.x; i < WCHUNKS; i += NTHREADS)
        CPA16(s_base + (uint32_t)(i * 16), gp + (size_t)i * 16);
    CPA_COMMIT();
}

// ---------------- prep kernels ----------------
__global__ void prep_plain(const float* __restrict__ Wgcn, const float* __restrict__ Wvm,
                           const float* __restrict__ Wvd,  const float* __restrict__ W1) {
    int slot4 = blockIdx.x >> 4;
    const float* W; int slot;
    switch (slot4) {
        case 0:  W = Wgcn; slot = 0; break;
        case 1:  W = Wvm;  slot = 3; break;
        case 2:  W = Wvd;  slot = 4; break;
        default: W = W1;   slot = 5; break;
    }
    int e0 = (blockIdx.x & 15) * 1024;
    for (int e = e0 + threadIdx.x; e < e0 + 1024; e += blockDim.x) {
        int n = e >> 7, k = e & 127;
        g_Wpad[slot][n * LDW + k] = __float2half_rn(W[k * CDIM + n]);
    }
}
__global__ void prep_gm(const float* __restrict__ Wq_m, const float* __restrict__ Wk_m,
                        const float* __restrict__ Wq_d, const float* __restrict__ Wk_d) {
    __shared__ float krow[CDIM];
    int which = blockIdx.x >> 7;
    int n = blockIdx.x & 127;
    const float* Wq = which ? Wq_d : Wq_m;
    const float* Wk = which ? Wk_d : Wk_m;
    if (threadIdx.x < CDIM) krow[threadIdx.x] = Wk[n * CDIM + threadIdx.x];
    __syncthreads();
    int k = threadIdx.x;
    const float4* q4 = reinterpret_cast<const float4*>(Wq + k * CDIM);
    float s = 0.f;
#pragma unroll
    for (int c4 = 0; c4 < CDIM / 4; ++c4) {
        float4 q = q4[c4];
        s = fmaf(q.x, krow[c4 * 4 + 0], s);
        s = fmaf(q.y, krow[c4 * 4 + 1], s);
        s = fmaf(q.z, krow[c4 * 4 + 2], s);
        s = fmaf(q.w, krow[c4 * 4 + 3], s);
    }
    g_Wpad[which ? 2 : 1][n * LDW + k] = __float2half_rn(s * 0.0883883476483184f);
}

// ---------------- SMEM layout ----------------
#define F_MS   0
#define F_DS   (BT * LDA)
#define F_X1M  (2 * BT * LDA)
#define F_X1D  (3 * BT * LDA)
#define WB0_BYTES (4 * BT * LDA * 4)                 // 135168
#define WB1_BYTES (WB0_BYTES + WCOMP_BYTES)          // 169984
#define F_R0   ((WB1_BYTES + WCOMP_BYTES) / 4)       // 51200
#define F_R1   (F_R0 + 512)
#define F_SAM  (F_R1 + 512)
#define F_SBM  (F_SAM + 64)
#define F_SAD  (F_SBM + 64)
#define F_SBD  (F_SAD + 64)
#define F_SW2  (F_SBD + 64)
#define SMEM_BYTES ((F_SW2 + 128) * 4)               // 210432

// ---------------- GEMM (single-term fp16: acc += cvt(x) @ W) ----------------
template<int COMB>
__device__ __forceinline__ void gemm_f16(const float* __restrict__ Xa, const float* __restrict__ Xb,
                                         float ca0, float cb0, float ca1, float cb1,
                                         uint32_t wb, int r0, int cK, float acc[8][4]) {
    const float* pa0 = Xa + r0 * LDA;
    const float* pa1 = Xa + (r0 + 8) * LDA;
    const float* pb0 = Xb + r0 * LDA;
    const float* pb1 = Xb + (r0 + 8) * LDA;
#pragma unroll
    for (int ks = 0; ks < 8; ++ks) {
        int c0 = ks * 16 + cK;
        uint32_t a[4];
        {
            float2 v0 = *reinterpret_cast<const float2*>(pa0 + c0);
            float2 v1 = *reinterpret_cast<const float2*>(pa1 + c0);
            float2 v2 = *reinterpret_cast<const float2*>(pa0 + c0 + 8);
            float2 v3 = *reinterpret_cast<const float2*>(pa1 + c0 + 8);
            if (COMB) {
                float2 u0 = *reinterpret_cast<const float2*>(pb0 + c0);
                float2 u1 = *reinterpret_cast<const float2*>(pb1 + c0);
                float2 u2 = *reinterpret_cast<const float2*>(pb0 + c0 + 8);
                float2 u3 = *reinterpret_cast<const float2*>(pb1 + c0 + 8);
                v0.x = ca0 * v0.x + cb0 * u0.x;  v0.y = ca0 * v0.y + cb0 * u0.y;
                v1.x = ca1 * v1.x + cb1 * u1.x;  v1.y = ca1 * v1.y + cb1 * u1.y;
                v2.x = ca0 * v2.x + cb0 * u2.x;  v2.y = ca0 * v2.y + cb0 * u2.y;
                v3.x = ca1 * v3.x + cb1 * u3.x;  v3.y = ca1 * v3.y + cb1 * u3.y;
            }
            a[0] = cvt2h(v0.x, v0.y);
            a[1] = cvt2h(v1.x, v1.y);
            a[2] = cvt2h(v2.x, v2.y);
            a[3] = cvt2h(v3.x, v3.y);
        }
#pragma unroll
        for (int np = 0; np < 4; ++np) {
            uint32_t off = (uint32_t)(np * (16 * 2 * LDW) + ks * 32);
            uint32_t b0_, b1_, b2_, b3_;
            LDSM4(b0_, b1_, b2_, b3_, wb + off);
            mma_f16(acc[np * 2],     a, b0_, b1_);
            mma_f16(acc[np * 2 + 1], a, b2_, b3_);
        }
    }
}

// merged GCN pass: u0 = a*m + b*d, u1 = b*m + a*d share loads and B fragments.
__device__ __forceinline__ void gemm_f16_dual(const float* __restrict__ Ms, const float* __restrict__ Ds,
                                              float a0, float b0c, float a1, float b1c,
                                              uint32_t wb, int r0, int cK,
                                              float acc0[8][4], float acc1[8][4]) {
    const float* pm0 = Ms + r0 * LDA;
    const float* pm1 = Ms + (r0 + 8) * LDA;
    const float* pd0 = Ds + r0 * LDA;
    const float* pd1 = Ds + (r0 + 8) * LDA;
#pragma unroll
    for (int ks = 0; ks < 8; ++ks) {
        int c0 = ks * 16 + cK;
        uint32_t x0[4], x1[4];
        {
            float2 m0 = *reinterpret_cast<const float2*>(pm0 + c0);
            float2 m1 = *reinterpret_cast<const float2*>(pm1 + c0);
            float2 m2 = *reinterpret_cast<const float2*>(pm0 + c0 + 8);
            float2 m3 = *reinterpret_cast<const float2*>(pm1 + c0 + 8);
            float2 d0 = *reinterpret_cast<const float2*>(pd0 + c0);
            float2 d1 = *reinterpret_cast<const float2*>(pd1 + c0);
            float2 d2 = *reinterpret_cast<const float2*>(pd0 + c0 + 8);
            float2 d3 = *reinterpret_cast<const float2*>(pd1 + c0 + 8);
            x0[0] = cvt2h(a0 * m0.x + b0c * d0.x, a0 * m0.y + b0c * d0.y);
            x0[1] = cvt2h(a1 * m1.x + b1c * d1.x, a1 * m1.y + b1c * d1.y);
            x0[2] = cvt2h(a0 * m2.x + b0c * d2.x, a0 * m2.y + b0c * d2.y);
            x0[3] = cvt2h(a1 * m3.x + b1c * d3.x, a1 * m3.y + b1c * d3.y);
            x1[0] = cvt2h(b0c * m0.x + a0 * d0.x, b0c * m0.y + a0 * d0.y);
            x1[1] = cvt2h(b1c * m1.x + a1 * d1.x, b1c * m1.y + a1 * d1.y);
            x1[2] = cvt2h(b0c * m2.x + a0 * d2.x, b0c * m2.y + a0 * d2.y);
            x1[3] = cvt2h(b1c * m3.x + a1 * d3.x, b1c * m3.y + a1 * d3.y);
        }
#pragma unroll
        for (int np = 0; np < 4; ++np) {
            uint32_t off = (uint32_t)(np * (16 * 2 * LDW) + ks * 32);
            uint32_t b0_, b1_, b2_, b3_;
            LDSM4(b0_, b1_, b2_, b3_, wb + off);
            mma_f16(acc0[np * 2],     x0, b0_, b1_);
            mma_f16(acc0[np * 2 + 1], x0, b2_, b3_);
            mma_f16(acc1[np * 2],     x1, b0_, b1_);
            mma_f16(acc1[np * 2 + 1], x1, b2_, b3_);
        }
    }
}

__global__ __launch_bounds__(NTHREADS, 1)
void mdi_mma_kernel(const float* __restrict__ em, const float* __restrict__ ed,
                    const float* __restrict__ W2, float* __restrict__ out) {
    extern __shared__ float sh[];
    float* Ms  = sh + F_MS;
    float* Ds  = sh + F_DS;
    float* X1m = sh + F_X1M;
    float* X1d = sh + F_X1D;
    uint32_t wb0_u = smem_u32(reinterpret_cast<char*>(sh) + WB0_BYTES);
    uint32_t wb1_u = smem_u32(reinterpret_cast<char*>(sh) + WB1_BYTES);
    float* R0  = sh + F_R0;
    float* R1  = sh + F_R1;
    float* SAm = sh + F_SAM;
    float* SBm = sh + F_SBM;
    float* SAd = sh + F_SAD;
    float* SBd = sh + F_SBD;
    float* SW2 = sh + F_SW2;

    const int tid  = threadIdx.x;
    const int w    = tid >> 5;
    const int lane = tid & 31;
    const int mb    = (w & 3) * 16;
    const int nbase = (w >> 2) * 64;
    const int r0    = mb + (lane >> 2);
    const int cK    = 2 * (lane & 3);
    const int half4 = (w >> 2) * 4;
    const int lq    = lane & 3;
    const int b0 = blockIdx.x * BT;

    const int n_lane = (lane & 7) + ((lane & 16) ? 8 : 0);
    const uint32_t laneoff = (uint32_t)((nbase + n_lane) * (2 * LDW) + ((lane >> 3) & 1) * 16);
    const uint32_t wb0 = wb0_u + laneoff;
    const uint32_t wb1 = wb1_u + laneoff;

    // prefetch W0 (Wgcn) -> B0, W1 (gM0) -> B1
    cpa_load(g_Wpad[0], wb0_u);
    cpa_load(g_Wpad[1], wb1_u);

    // ---- load inputs (padded) + W2 ----
    {
        const float4* gm = reinterpret_cast<const float4*>(em + (size_t)b0 * CDIM);
        const float4* gd = reinterpret_cast<const float4*>(ed + (size_t)b0 * CDIM);
        for (int i = tid; i < BT * 32; i += NTHREADS) {
            int row = i >> 5, c = i & 31;
            *reinterpret_cast<float4*>(&Ms[row * LDA + c * 4]) = gm[i];
            *reinterpret_cast<float4*>(&Ds[row * LDA + c * 4]) = gd[i];
        }
        if (tid < CDIM) SW2[tid] = W2[tid];
    }
    __syncthreads();

    // ---- per-batch scalars -> SAm (diag a), SBm (offdiag b) ----
    {
        int rr = tid >> 2, part = tid & 3;
        const float* mr = Ms + rr * LDA;
        const float* dr = Ds + rr * LDA;
        float dman = 0.f, sm2 = 0.f, sd2 = 0.f, md = 0.f;
        int k0 = part * 32;
#pragma unroll
        for (int k = 0; k < 32; k += 4) {
            float4 mv = *reinterpret_cast<const float4*>(mr + k0 + k);
            float4 dv = *reinterpret_cast<const float4*>(dr + k0 + k);
            dman += fabsf(mv.x - dv.x) + fabsf(mv.y - dv.y) + fabsf(mv.z - dv.z) + fabsf(mv.w - dv.w);
            sm2 += mv.x * mv.x + mv.y * mv.y + mv.z * mv.z + mv.w * mv.w;
            sd2 += dv.x * dv.x + dv.y * dv.y + dv.z * dv.z + dv.w * dv.w;
            md  += mv.x * dv.x + mv.y * dv.y + mv.z * dv.z + mv.w * dv.w;
        }
        R0[rr * 4 + part] = dman;
        R0[256 + rr * 4 + part] = sm2;
        R1[rr * 4 + part] = sd2;
        R1[256 + rr * 4 + part] = md;
    }
    __syncthreads();
    if (tid < BT) {
        int b4 = tid * 4;
        float dman = R0[b4] + R0[b4 + 1] + R0[b4 + 2] + R0[b4 + 3];
        float sm2  = R0[256 + b4] + R0[257 + b4] + R0[258 + b4] + R0[259 + b4];
        float sd2  = R1[b4] + R1[b4 + 1] + R1[b4 + 2] + R1[b4 + 3];
        float md   = R1[256 + b4] + R1[257 + b4] + R1[258 + b4] + R1[259 + b4];
        float s3 = 1.f / (1.f + dman);
        float c = md / (sqrtf(sm2 + EPSF) * sqrtf(sd2 + EPSF));
        if (c < 0.f) c *= 0.01f;
        float s1 = 1.f / (1.f + c);
        SAm[tid] = fminf(s3, s1);
        SBm[tid] = fminf(dman * s3, c * s1);
    }
    __syncthreads();

    // ===== pass 0 (merged GCN): x1m/x1d = relu(u @ Wgcn) + x0 =====
    CPA_WAIT(1); __syncthreads();        // W0 ready (W1 outstanding)
    {
        float acc0[8][4] = {}, acc1[8][4] = {};
        gemm_f16_dual(Ms, Ds, SAm[r0], SBm[r0], SAm[r0 + 8], SBm[r0 + 8],
                      wb0, r0, cK, acc0, acc1);
        __syncthreads();
        cpa_load(g_Wpad[2], wb0_u);      // gM1 -> B0
#pragma unroll
        for (int nt = 0; nt < 8; ++nt) {
            int col = nbase + nt * 8 + cK;
            float2 m0 = *reinterpret_cast<const float2*>(&Ms[r0 * LDA + col]);
            float2 m1 = *reinterpret_cast<const float2*>(&Ms[(r0 + 8) * LDA + col]);
            float2 d0 = *reinterpret_cast<const float2*>(&Ds[r0 * LDA + col]);
            float2 d1 = *reinterpret_cast<const float2*>(&Ds[(r0 + 8) * LDA + col]);
            *reinterpret_cast<float2*>(&X1m[r0 * LDA + col]) =
                make_float2(fmaxf(acc0[nt][0], 0.f) + m0.x, fmaxf(acc0[nt][1], 0.f) + m0.y);
            *reinterpret_cast<float2*>(&X1m[(r0 + 8) * LDA + col]) =
                make_float2(fmaxf(acc0[nt][2], 0.f) + m1.x, fmaxf(acc0[nt][3], 0.f) + m1.y);
            *reinterpret_cast<float2*>(&X1d[r0 * LDA + col]) =
                make_float2(fmaxf(acc1[nt][0], 0.f) + d0.x, fmaxf(acc1[nt][1], 0.f) + d0.y);
            *reinterpret_cast<float2*>(&X1d[(r0 + 8) * LDA + col]) =
                make_float2(fmaxf(acc1[nt][2], 0.f) + d1.x, fmaxf(acc1[nt][3], 0.f) + d1.y);
        }
    }

    // ===== passes 1/2: attention scores per branch (scale folded into gM) =====
#pragma unroll 1
    for (int br = 0; br < 2; ++br) {
        float* X1 = br ? X1d : X1m;
        float* X0 = br ? Ds : Ms;
        uint32_t wb = br ? wb0 : wb1;    // gM0 in B1, gM1 in B0
        float acc[8][4] = {};
        CPA_WAIT(1); __syncthreads();    // current gM ready
        gemm_f16<0>(X1, X1, 0.f, 0.f, 0.f, 0.f, wb, r0, cK, acc);
        __syncthreads();
        cpa_load(g_Wpad[br ? 4 : 3], br ? wb0_u : wb1_u);   // Wv_m -> B1, Wv_d -> B0
        // score partials
        {
            float q00 = 0.f, q10 = 0.f, q01 = 0.f, q11 = 0.f;
#pragma unroll
            for (int nt = 0; nt < 8; ++nt) {
                int col = nbase + nt * 8 + cK;
                float2 a0 = *reinterpret_cast<const float2*>(&X0[r0 * LDA + col]);
                float2 a1 = *reinterpret_cast<const float2*>(&X1[r0 * LDA + col]);
                float2 c0 = *reinterpret_cast<const float2*>(&X0[(r0 + 8) * LDA + col]);
                float2 c1 = *reinterpret_cast<const float2*>(&X1[(r0 + 8) * LDA + col]);
                q00 += acc[nt][0] * a0.x + acc[nt][1] * a0.y;
                q10 += acc[nt][0] * a1.x + acc[nt][1] * a1.y;
                q01 += acc[nt][2] * c0.x + acc[nt][3] * c0.y;
                q11 += acc[nt][2] * c1.x + acc[nt][3] * c1.y;
            }
            R0[r0 * 8 + half4 + lq] = q00;
            R1[r0 * 8 + half4 + lq] = q10;
            R0[(r0 + 8) * 8 + half4 + lq] = q01;
            R1[(r0 + 8) * 8 + half4 + lq] = q11;
        }
        __syncthreads();
        if (tid < BT) {
            float s0 = 0.f, s1v = 0.f;
#pragma unroll
            for (int g = 0; g < 8; ++g) { s0 += R0[tid * 8 + g]; s1v += R1[tid * 8 + g]; }
            float mx = fmaxf(s0, s1v);
            float e0 = __expf(s0 - mx), e1 = __expf(s1v - mx);
            float inv = 1.f / (e0 + e1);
            if (br == 0) { SAm[tid] = e0 * inv; SBm[tid] = e1 * inv; }
            else         { SAd[tid] = e0 * inv; SBd[tid] = e1 * inv; }
        }
    }

    // ===== pass 3: mLA = (a0m*x0m + a1m*x1m) @ Wv_m, kept in registers =====
    float mla[8][4] = {};
    CPA_WAIT(1); __syncthreads();        // Wv_m (B1) ready
    gemm_f16<1>(Ms, X1m, SAm[r0], SBm[r0], SAm[r0 + 8], SBm[r0 + 8], wb1, r0, cK, mla);
    __syncthreads();
    cpa_load(g_Wpad[5], wb1_u);          // W1 -> B1

    // ===== pass 4: ne = ((a0d*x0d + a1d*x1d) @ Wv_d) * mLA -> X1m =====
    {
        float acc[8][4] = {};
        CPA_WAIT(1); __syncthreads();    // Wv_d (B0) ready
        gemm_f16<1>(Ds, X1d, SAd[r0], SBd[r0], SAd[r0 + 8], SBd[r0 + 8], wb0, r0, cK, acc);
#pragma unroll
        for (int nt = 0; nt < 8; ++nt) {
            int col = nbase + nt * 8 + cK;
            *reinterpret_cast<float2*>(&X1m[r0 * LDA + col]) =
                make_float2(acc[nt][0] * mla[nt][0], acc[nt][1] * mla[nt][1]);
            *reinterpret_cast<float2*>(&X1m[(r0 + 8) * LDA + col]) =
                make_float2(acc[nt][2] * mla[nt][2], acc[nt][3] * mla[nt][3]);
        }
    }

    // ===== pass 5: pre = relu(ne @ W1) . W2 ; out = sigmoid =====
    {
        float acc[8][4] = {};
        CPA_WAIT(0); __syncthreads();    // W1 (B1) ready; also orders ne writes
        gemm_f16<0>(X1m, X1m, 0.f, 0.f, 0.f, 0.f, wb1, r0, cK, acc);
        float p0 = 0.f, p1 = 0.f;
#pragma unroll
        for (int nt = 0; nt < 8; ++nt) {
            int col = nbase + nt * 8 + cK;
            p0 += fmaxf(acc[nt][0], 0.f) * SW2[col] + fmaxf(acc[nt][1], 0.f) * SW2[col + 1];
            p1 += fmaxf(acc[nt][2], 0.f) * SW2[col] + fmaxf(acc[nt][3], 0.f) * SW2[col + 1];
        }
        R0[r0 * 8 + half4 + lq] = p0;
        R0[(r0 + 8) * 8 + half4 + lq] = p1;
    }
    __syncthreads();
    if (tid < BT) {
        float pre = 0.f;
#pragma unroll
        for (int g = 0; g < 8; ++g) pre += R0[tid * 8 + g];
        out[b0 + tid] = 1.f / (1.f + __expf(-pre));
    }
}

extern "C" void kernel_launch(void* const* d_in, const int* in_sizes, int n_in,
                              void* d_out, int out_size) {
    const float* em    = (const float*)d_in[0];
    const float* ed    = (const float*)d_in[1];
    const float* Wgcn  = (const float*)d_in[2];
    const float* Wq_m  = (const float*)d_in[3];
    const float* Wk_m  = (const float*)d_in[4];
    const float* Wv_m  = (const float*)d_in[5];
    const float* Wq_d  = (const float*)d_in[6];
    const float* Wk_d  = (const float*)d_in[7];
    const float* Wv_d  = (const float*)d_in[8];
    const float* W1    = (const float*)d_in[9];
    const float* W2    = (const float*)d_in[10];
    float* out = (float*)d_out;

    cudaFuncSetAttribute(mdi_mma_kernel, cudaFuncAttributeMaxDynamicSharedMemorySize, SMEM_BYTES);

    int B = out_size;   // 262144
    prep_plain<<<64, 256>>>(Wgcn, Wv_m, Wv_d, W1);
    prep_gm<<<256, 128>>>(Wq_m, Wk_m, Wq_d, Wk_d);
    mdi_mma_kernel<<<B / BT, NTHREADS, SMEM_BYTES>>>(em, ed, W2, out);
}

// round 9
// speedup vs baseline: 9.6239x; 2.0085x over previous
#include <cuda_runtime.h>
#include <cuda_fp16.h>
#include <cstdint>
#include <math.h>

#define CDIM 128
#define BT   64
#define LDH  136            // fp16 tile row stride (272B: conflict-free, 16B aligned)
#define LDW  136            // fp16 weight row stride
#define NTHREADS 256
#define EPSF 1e-8f
#define WCOMP_BYTES (CDIM * LDW * 2)   // 34816 bytes per weight image
#define WCHUNKS (WCOMP_BYTES / 16)     // 2176

// Weight images, fp16, B[n][k] = W[k][n] (padded rows).
// slots: 0=Wgcn 1=gM0(Wq_m@Wk_m^T/sqrtC) 2=gM1 3=Wv_m 4=Wv_d 5=W1
__device__ __align__(16) __half g_Wpad[6][CDIM * LDW];

// ---------------- helpers ----------------
__device__ __forceinline__ uint32_t smem_u32(const void* p) {
    uint32_t a;
    asm("{ .reg .u64 t; cvta.to.shared.u64 t, %1; cvt.u32.u64 %0, t; }" : "=r"(a) : "l"(p));
    return a;
}
__device__ __forceinline__ uint32_t cvt2h(float a, float b) {
    __half2 h = __floats2half2_rn(a, b);
    return *reinterpret_cast<uint32_t*>(&h);
}
__device__ __forceinline__ float2 up2(const __half* p) {
    return __half22float2(*reinterpret_cast<const __half2*>(p));
}
__device__ __forceinline__ void mma_f16(float c[4], const uint32_t a[4], uint32_t b0, uint32_t b1) {
    asm volatile("mma.sync.aligned.m16n8k16.row.col.f32.f16.f16.f32 "
        "{%0,%1,%2,%3}, {%4,%5,%6,%7}, {%8,%9}, {%0,%1,%2,%3};"
        : "+f"(c[0]), "+f"(c[1]), "+f"(c[2]), "+f"(c[3])
        : "r"(a[0]), "r"(a[1]), "r"(a[2]), "r"(a[3]), "r"(b0), "r"(b1));
}
#define LDSM4(r0_, r1_, r2_, r3_, addr) asm volatile( \
    "ldmatrix.sync.aligned.m8n8.x4.shared.b16 {%0,%1,%2,%3}, [%4];" \
    : "=r"(r0_), "=r"(r1_), "=r"(r2_), "=r"(r3_) : "r"(addr))

#define CPA16(s, g)   asm volatile("cp.async.cg.shared.global [%0], [%1], 16;" :: "r"(s), "l"(g))
#define CPA_COMMIT()  asm volatile("cp.async.commit_group;" ::: "memory")
#define CPA_WAIT(n)   asm volatile("cp.async.wait_group %0;" :: "n"(n) : "memory")

__device__ __forceinline__ void cpa_load(const __half* g, uint32_t s_base) {
    const char* gp = reinterpret_cast<const char*>(g);
    for (int i = threadIdx.x; i < WCHUNKS; i += NTHREADS)
        CPA16(s_base + (uint32_t)(i * 16), gp + (size_t)i * 16);
    CPA_COMMIT();
}

// ---------------- merged prep kernel (2 launches/iter -> ncu -s5 hits main) ----
__global__ void prep_all(const float* __restrict__ Wgcn, const float* __restrict__ Wvm,
                         const float* __restrict__ Wvd,  const float* __restrict__ W1,
                         const float* __restrict__ Wq_m, const float* __restrict__ Wk_m,
                         const float* __restrict__ Wq_d, const float* __restrict__ Wk_d) {
    int b = blockIdx.x;
    if (b < 64) {
        int slot4 = b >> 4;
        const float* W; int slot;
        switch (slot4) {
            case 0:  W = Wgcn; slot = 0; break;
            case 1:  W = Wvm;  slot = 3; break;
            case 2:  W = Wvd;  slot = 4; break;
            default: W = W1;   slot = 5; break;
        }
        int e0 = (b & 15) * 1024;
        for (int e = e0 + threadIdx.x; e < e0 + 1024; e += blockDim.x) {
            int n = e >> 7, k = e & 127;
            g_Wpad[slot][n * LDW + k] = __float2half_rn(W[k * CDIM + n]);
        }
    } else {
        __shared__ float krow[CDIM];
        int bb = b - 64;
        int which = bb >> 7;
        int n = bb & 127;
        const float* Wq = which ? Wq_d : Wq_m;
        const float* Wk = which ? Wk_d : Wk_m;
        if (threadIdx.x < CDIM) krow[threadIdx.x] = Wk[n * CDIM + threadIdx.x];
        __syncthreads();
        if (threadIdx.x < CDIM) {
            int k = threadIdx.x;
            const float4* q4 = reinterpret_cast<const float4*>(Wq + k * CDIM);
            float s = 0.f;
#pragma unroll
            for (int c4 = 0; c4 < CDIM / 4; ++c4) {
                float4 q = q4[c4];
                s = fmaf(q.x, krow[c4 * 4 + 0], s);
                s = fmaf(q.y, krow[c4 * 4 + 1], s);
                s = fmaf(q.z, krow[c4 * 4 + 2], s);
                s = fmaf(q.w, krow[c4 * 4 + 3], s);
            }
            g_Wpad[which ? 2 : 1][n * LDW + k] = __float2half_rn(s * 0.0883883476483184f);
        }
    }
}

// ---------------- SMEM layout (all tiles fp16) ----------------
#define H_MS   0
#define H_DS   (BT * LDH)                 // 8704 halves
#define H_X1M  (2 * BT * LDH)
#define H_X1D  (3 * BT * LDH)
#define WB_BYTES (4 * BT * LDH * 2)       // 69632
#define F_R0   ((WB_BYTES + WCOMP_BYTES) / 4)   // 26112 floats
#define F_R1   (F_R0 + 512)
#define F_SAM  (F_R1 + 512)
#define F_SBM  (F_SAM + 64)
#define F_SAD  (F_SBM + 64)
#define F_SBD  (F_SAD + 64)
#define F_SW2  (F_SBD + 64)
#define SMEM_BYTES ((F_SW2 + 128) * 4)    // 110080 -> 2 CTAs/SM

// ---------------- GEMM (fp16 tiles) ----------------
// non-COMB: A-fragments are raw 4B loads (zero conversion).
// COMB: A row r = ca(r)*Xa[r] + cb(r)*Xb[r] built in fp32, cvt to fp16.
template<int COMB>
__device__ __forceinline__ void gemm_h(const __half* __restrict__ Xa, const __half* __restrict__ Xb,
                                       float ca0, float cb0, float ca1, float cb1,
                                       uint32_t wb, int r0, int cK, float acc[8][4]) {
    const __half* pa0 = Xa + r0 * LDH;
    const __half* pa1 = Xa + (r0 + 8) * LDH;
    const __half* pb0 = Xb + r0 * LDH;
    const __half* pb1 = Xb + (r0 + 8) * LDH;
#pragma unroll
    for (int ks = 0; ks < 8; ++ks) {
        int c0 = ks * 16 + cK;
        uint32_t a[4];
        if (!COMB) {
            a[0] = *reinterpret_cast<const uint32_t*>(pa0 + c0);
            a[1] = *reinterpret_cast<const uint32_t*>(pa1 + c0);
            a[2] = *reinterpret_cast<const uint32_t*>(pa0 + c0 + 8);
            a[3] = *reinterpret_cast<const uint32_t*>(pa1 + c0 + 8);
        } else {
            float2 v0 = up2(pa0 + c0), u0 = up2(pb0 + c0);
            float2 v1 = up2(pa1 + c0), u1 = up2(pb1 + c0);
            float2 v2 = up2(pa0 + c0 + 8), u2 = up2(pb0 + c0 + 8);
            float2 v3 = up2(pa1 + c0 + 8), u3 = up2(pb1 + c0 + 8);
            a[0] = cvt2h(ca0 * v0.x + cb0 * u0.x, ca0 * v0.y + cb0 * u0.y);
            a[1] = cvt2h(ca1 * v1.x + cb1 * u1.x, ca1 * v1.y + cb1 * u1.y);
            a[2] = cvt2h(ca0 * v2.x + cb0 * u2.x, ca0 * v2.y + cb0 * u2.y);
            a[3] = cvt2h(ca1 * v3.x + cb1 * u3.x, ca1 * v3.y + cb1 * u3.y);
        }
#pragma unroll
        for (int np = 0; np < 4; ++np) {
            uint32_t off = (uint32_t)(np * (16 * 2 * LDW) + ks * 32);
            uint32_t b0_, b1_, b2_, b3_;
            LDSM4(b0_, b1_, b2_, b3_, wb + off);
            mma_f16(acc[np * 2],     a, b0_, b1_);
            mma_f16(acc[np * 2 + 1], a, b2_, b3_);
        }
    }
}

// merged GCN pass: u0 = a*m + b*d, u1 = b*m + a*d share loads and B fragments.
__device__ __forceinline__ void gemm_h_dual(const __half* __restrict__ Ms, const __half* __restrict__ Ds,
                                            float a0, float b0c, float a1, float b1c,
                                            uint32_t wb, int r0, int cK,
                                            float acc0[8][4], float acc1[8][4]) {
    const __half* pm0 = Ms + r0 * LDH;
    const __half* pm1 = Ms + (r0 + 8) * LDH;
    const __half* pd0 = Ds + r0 * LDH;
    const __half* pd1 = Ds + (r0 + 8) * LDH;
#pragma unroll
    for (int ks = 0; ks < 8; ++ks) {
        int c0 = ks * 16 + cK;
        uint32_t x0[4], x1[4];
        {
            float2 m0 = up2(pm0 + c0), d0 = up2(pd0 + c0);
            float2 m1 = up2(pm1 + c0), d1 = up2(pd1 + c0);
            float2 m2 = up2(pm0 + c0 + 8), d2 = up2(pd0 + c0 + 8);
            float2 m3 = up2(pm1 + c0 + 8), d3 = up2(pd1 + c0 + 8);
            x0[0] = cvt2h(a0 * m0.x + b0c * d0.x, a0 * m0.y + b0c * d0.y);
            x0[1] = cvt2h(a1 * m1.x + b1c * d1.x, a1 * m1.y + b1c * d1.y);
            x0[2] = cvt2h(a0 * m2.x + b0c * d2.x, a0 * m2.y + b0c * d2.y);
            x0[3] = cvt2h(a1 * m3.x + b1c * d3.x, a1 * m3.y + b1c * d3.y);
            x1[0] = cvt2h(b0c * m0.x + a0 * d0.x, b0c * m0.y + a0 * d0.y);
            x1[1] = cvt2h(b1c * m1.x + a1 * d1.x, b1c * m1.y + a1 * d1.y);
            x1[2] = cvt2h(b0c * m2.x + a0 * d2.x, b0c * m2.y + a0 * d2.y);
            x1[3] = cvt2h(b1c * m3.x + a1 * d3.x, b1c * m3.y + a1 * d3.y);
        }
#pragma unroll
        for (int np = 0; np < 4; ++np) {
            uint32_t off = (uint32_t)(np * (16 * 2 * LDW) + ks * 32);
            uint32_t b0_, b1_, b2_, b3_;
            LDSM4(b0_, b1_, b2_, b3_, wb + off);
            mma_f16(acc0[np * 2],     x0, b0_, b1_);
            mma_f16(acc0[np * 2 + 1], x0, b2_, b3_);
            mma_f16(acc1[np * 2],     x1, b0_, b1_);
            mma_f16(acc1[np * 2 + 1], x1, b2_, b3_);
        }
    }
}

__global__ __launch_bounds__(NTHREADS, 2)
void mdi_mma_kernel(const float* __restrict__ em, const float* __restrict__ ed,
                    const float* __restrict__ W2, float* __restrict__ out) {
    extern __shared__ float sh[];
    __half* Ms  = reinterpret_cast<__half*>(sh) + H_MS;
    __half* Ds  = reinterpret_cast<__half*>(sh) + H_DS;
    __half* X1m = reinterpret_cast<__half*>(sh) + H_X1M;
    __half* X1d = reinterpret_cast<__half*>(sh) + H_X1D;
    uint32_t wb_u = smem_u32(reinterpret_cast<char*>(sh) + WB_BYTES);
    float* R0  = sh + F_R0;
    float* R1  = sh + F_R1;
    float* SAm = sh + F_SAM;
    float* SBm = sh + F_SBM;
    float* SAd = sh + F_SAD;
    float* SBd = sh + F_SBD;
    float* SW2 = sh + F_SW2;

    const int tid  = threadIdx.x;
    const int w    = tid >> 5;
    const int lane = tid & 31;
    const int mb    = (w & 3) * 16;
    const int nbase = (w >> 2) * 64;
    const int r0    = mb + (lane >> 2);
    const int cK    = 2 * (lane & 3);
    const int half4 = (w >> 2) * 4;
    const int lq    = lane & 3;
    const int b0 = blockIdx.x * BT;

    const int n_lane = (lane & 7) + ((lane & 16) ? 8 : 0);
    const uint32_t laneoff = (uint32_t)((nbase + n_lane) * (2 * LDW) + ((lane >> 3) & 1) * 16);
    const uint32_t wb = wb_u + laneoff;

    // prefetch Wgcn
    cpa_load(g_Wpad[0], wb_u);

    // ---- load inputs -> fp16 tiles, + W2 ----
    {
        const float4* gm = reinterpret_cast<const float4*>(em + (size_t)b0 * CDIM);
        const float4* gd = reinterpret_cast<const float4*>(ed + (size_t)b0 * CDIM);
        for (int i = tid; i < BT * 32; i += NTHREADS) {
            int row = i >> 5, c = i & 31;
            float4 vm = gm[i], vd = gd[i];
            uint2 pm = make_uint2(cvt2h(vm.x, vm.y), cvt2h(vm.z, vm.w));
            uint2 pd = make_uint2(cvt2h(vd.x, vd.y), cvt2h(vd.z, vd.w));
            *reinterpret_cast<uint2*>(Ms + row * LDH + c * 4) = pm;
            *reinterpret_cast<uint2*>(Ds + row * LDH + c * 4) = pd;
        }
        if (tid < CDIM) SW2[tid] = W2[tid];
    }
    __syncthreads();

    // ---- per-batch scalars -> SAm (diag a), SBm (offdiag b) ----
    {
        int rr = tid >> 2, part = tid & 3;
        const __half2* mr = reinterpret_cast<const __half2*>(Ms + rr * LDH + part * 32);
        const __half2* dr = reinterpret_cast<const __half2*>(Ds + rr * LDH + part * 32);
        float dman = 0.f, sm2 = 0.f, sd2 = 0.f, md = 0.f;
#pragma unroll
        for (int k = 0; k < 16; ++k) {
            float2 mv = __half22float2(mr[k]);
            float2 dv = __half22float2(dr[k]);
            dman += fabsf(mv.x - dv.x) + fabsf(mv.y - dv.y);
            sm2 += mv.x * mv.x + mv.y * mv.y;
            sd2 += dv.x * dv.x + dv.y * dv.y;
            md  += mv.x * dv.x + mv.y * dv.y;
        }
        R0[rr * 4 + part] = dman;
        R0[256 + rr * 4 + part] = sm2;
        R1[rr * 4 + part] = sd2;
        R1[256 + rr * 4 + part] = md;
    }
    __syncthreads();
    if (tid < BT) {
        int b4 = tid * 4;
        float dman = R0[b4] + R0[b4 + 1] + R0[b4 + 2] + R0[b4 + 3];
        float sm2  = R0[256 + b4] + R0[257 + b4] + R0[258 + b4] + R0[259 + b4];
        float sd2  = R1[b4] + R1[b4 + 1] + R1[b4 + 2] + R1[b4 + 3];
        float md   = R1[256 + b4] + R1[257 + b4] + R1[258 + b4] + R1[259 + b4];
        float s3 = 1.f / (1.f + dman);
        float c = md / (sqrtf(sm2 + EPSF) * sqrtf(sd2 + EPSF));
        if (c < 0.f) c *= 0.01f;
        float s1 = 1.f / (1.f + c);
        SAm[tid] = fminf(s3, s1);
        SBm[tid] = fminf(dman * s3, c * s1);
    }
    CPA_WAIT(0);
    __syncthreads();      // Wgcn ready + scalars visible

    // ===== pass 0 (merged GCN): x1m/x1d = relu(u @ Wgcn) + x0 =====
    {
        float acc0[8][4] = {}, acc1[8][4] = {};
        gemm_h_dual(Ms, Ds, SAm[r0], SBm[r0], SAm[r0 + 8], SBm[r0 + 8],
                    wb, r0, cK, acc0, acc1);
        __syncthreads();                 // all warps done with Wgcn
        cpa_load(g_Wpad[1], wb_u);       // gM0
#pragma unroll
        for (int nt = 0; nt < 8; ++nt) {
            int col = nbase + nt * 8 + cK;
            float2 m0 = up2(&Ms[r0 * LDH + col]);
            float2 m1 = up2(&Ms[(r0 + 8) * LDH + col]);
            float2 d0 = up2(&Ds[r0 * LDH + col]);
            float2 d1 = up2(&Ds[(r0 + 8) * LDH + col]);
            *reinterpret_cast<uint32_t*>(&X1m[r0 * LDH + col]) =
                cvt2h(fmaxf(acc0[nt][0], 0.f) + m0.x, fmaxf(acc0[nt][1], 0.f) + m0.y);
            *reinterpret_cast<uint32_t*>(&X1m[(r0 + 8) * LDH + col]) =
                cvt2h(fmaxf(acc0[nt][2], 0.f) + m1.x, fmaxf(acc0[nt][3], 0.f) + m1.y);
            *reinterpret_cast<uint32_t*>(&X1d[r0 * LDH + col]) =
                cvt2h(fmaxf(acc1[nt][0], 0.f) + d0.x, fmaxf(acc1[nt][1], 0.f) + d0.y);
            *reinterpret_cast<uint32_t*>(&X1d[(r0 + 8) * LDH + col]) =
                cvt2h(fmaxf(acc1[nt][2], 0.f) + d1.x, fmaxf(acc1[nt][3], 0.f) + d1.y);
        }
    }

    // ===== passes 1/2: attention scores per branch (scale folded into gM) =====
#pragma unroll 1
    for (int br = 0; br < 2; ++br) {
        const __half* X1 = br ? X1d : X1m;
        const __half* X0 = br ? Ds : Ms;
        float acc[8][4] = {};
        CPA_WAIT(0); __syncthreads();    // current gM ready (+ X1 writes visible)
        gemm_h<0>(X1, X1, 0.f, 0.f, 0.f, 0.f, wb, r0, cK, acc);
        __syncthreads();                 // done reading weights
        cpa_load(g_Wpad[br ? 3 : 2], wb_u);   // gM1 then Wv_m
        {
            float q00 = 0.f, q10 = 0.f, q01 = 0.f, q11 = 0.f;
#pragma unroll
            for (int nt = 0; nt < 8; ++nt) {
                int col = nbase + nt * 8 + cK;
                float2 a0 = up2(&X0[r0 * LDH + col]);
                float2 a1 = up2(&X1[r0 * LDH + col]);
                float2 c0 = up2(&X0[(r0 + 8) * LDH + col]);
                float2 c1 = up2(&X1[(r0 + 8) * LDH + col]);
                q00 += acc[nt][0] * a0.x + acc[nt][1] * a0.y;
                q10 += acc[nt][0] * a1.x + acc[nt][1] * a1.y;
                q01 += acc[nt][2] * c0.x + acc[nt][3] * c0.y;
                q11 += acc[nt][2] * c1.x + acc[nt][3] * c1.y;
            }
            R0[r0 * 8 + half4 + lq] = q00;
            R1[r0 * 8 + half4 + lq] = q10;
            R0[(r0 + 8) * 8 + half4 + lq] = q01;
            R1[(r0 + 8) * 8 + half4 + lq] = q11;
        }
        __syncthreads();
        if (tid < BT) {
            float s0 = 0.f, s1v = 0.f;
#pragma unroll
            for (int g = 0; g < 8; ++g) { s0 += R0[tid * 8 + g]; s1v += R1[tid * 8 + g]; }
            float mx = fmaxf(s0, s1v);
            float e0 = __expf(s0 - mx), e1 = __expf(s1v - mx);
            float inv = 1.f / (e0 + e1);
            if (br == 0) { SAm[tid] = e0 * inv; SBm[tid] = e1 * inv; }
            else         { SAd[tid] = e0 * inv; SBd[tid] = e1 * inv; }
        }
    }

    // ===== pass 3: mLA = (a0m*x0m + a1m*x1m) @ Wv_m, kept in registers =====
    float mla[8][4] = {};
    CPA_WAIT(0); __syncthreads();        // Wv_m ready + SAm/SBm visible
    gemm_h<1>(Ms, X1m, SAm[r0], SBm[r0], SAm[r0 + 8], SBm[r0 + 8], wb, r0, cK, mla);
    __syncthreads();
    cpa_load(g_Wpad[4], wb_u);           // Wv_d

    // ===== pass 4: ne = ((a0d*x0d + a1d*x1d) @ Wv_d) * mLA -> X1m =====
    {
        float acc[8][4] = {};
        CPA_WAIT(0); __syncthreads();
        gemm_h<1>(Ds, X1d, SAd[r0], SBd[r0], SAd[r0 + 8], SBd[r0 + 8], wb, r0, cK, acc);
        __syncthreads();
        cpa_load(g_Wpad[5], wb_u);       // W1
#pragma unroll
        for (int nt = 0; nt < 8; ++nt) {
            int col = nbase + nt * 8 + cK;
            *reinterpret_cast<uint32_t*>(&X1m[r0 * LDH + col]) =
                cvt2h(acc[nt][0] * mla[nt][0], acc[nt][1] * mla[nt][1]);
            *reinterpret_cast<uint32_t*>(&X1m[(r0 + 8) * LDH + col]) =
                cvt2h(acc[nt][2] * mla[nt][2], acc[nt][3] * mla[nt][3]);
        }
    }

    // ===== pass 5: pre = relu(ne @ W1) . W2 ; out = sigmoid =====
    {
        float acc[8][4] = {};
        CPA_WAIT(0); __syncthreads();    // W1 ready + ne writes visible
        gemm_h<0>(X1m, X1m, 0.f, 0.f, 0.f, 0.f, wb, r0, cK, acc);
        float p0 = 0.f, p1 = 0.f;
#pragma unroll
        for (int nt = 0; nt < 8; ++nt) {
            int col = nbase + nt * 8 + cK;
            p0 += fmaxf(acc[nt][0], 0.f) * SW2[col] + fmaxf(acc[nt][1], 0.f) * SW2[col + 1];
            p1 += fmaxf(acc[nt][2], 0.f) * SW2[col] + fmaxf(acc[nt][3], 0.f) * SW2[col + 1];
        }
        R0[r0 * 8 + half4 + lq] = p0;
        R0[(r0 + 8) * 8 + half4 + lq] = p1;
    }
    __syncthreads();
    if (tid < BT) {
        float pre = 0.f;
#pragma unroll
        for (int g = 0; g < 8; ++g) pre += R0[tid * 8 + g];
        out[b0 + tid] = 1.f / (1.f + __expf(-pre));
    }
}

extern "C" void kernel_launch(void* const* d_in, const int* in_sizes, int n_in,
                              void* d_out, int out_size) {
    const float* em    = (const float*)d_in[0];
    const float* ed    = (const float*)d_in[1];
    const float* Wgcn  = (const float*)d_in[2];
    const float* Wq_m  = (const float*)d_in[3];
    const float* Wk_m  = (const float*)d_in[4];
    const float* Wv_m  = (const float*)d_in[5];
    const float* Wq_d  = (const float*)d_in[6];
    const float* Wk_d  = (const float*)d_in[7];
    const float* Wv_d  = (const float*)d_in[8];
    const float* W1    = (const float*)d_in[9];
    const float* W2    = (const float*)d_in[10];
    float* out = (float*)d_out;

    cudaFuncSetAttribute(mdi_mma_kernel, cudaFuncAttributeMaxDynamicSharedMemorySize, SMEM_BYTES);

    int B = out_size;   // 262144
    prep_all<<<320, 256>>>(Wgcn, Wv_m, Wv_d, W1, Wq_m, Wk_m, Wq_d, Wk_d);
    mdi_mma_kernel<<<B / BT, NTHREADS, SMEM_BYTES>>>(em, ed, W2, out);
}